// round 7
// baseline (speedup 1.0000x reference)
#include <cuda_runtime.h>
#include <cuda_bf16.h>
#include <mma.h>

using namespace nvcuda;

#define IN_D 256
#define RU   128
#define OD   64
#define NB   2048
#define DDIM 32896
#define HCONST 0.5f
#define EPS_C  1e-8f
#define LN_EPS_C 1e-5f

typedef unsigned long long ull;

// ---------------- device scratch (allocation-free) ----------------
__device__ float    g_S  [IN_D*RU];
__device__ float    g_CS [IN_D*RU];
__device__ float    g_K2 [RU];
__device__ float    g_G  [OD];
__device__ float    g_Bc [OD];
__device__ float    g_fsT[RU*NB];      // (frs*rstd) transposed: [r][b]
__device__ float    g_c0 [NB];         // -mu*rstd
__device__ float    g_Wt [OD*RU];      // tail weights gamma*W[o][32768+r]
__device__ unsigned g_Bhi[256*4096];   // B hi split [i=256][n_w=4096] bf16x2, n_w = o*64 + r/2
__device__ unsigned g_Blo[256*4096];
__device__ unsigned g_Xhi[NB*128];     // X hi split [b][128 words]
__device__ unsigned g_Xlo[NB*128];

// ---------------- helpers ----------------
__device__ __forceinline__ ull pk2(float x){
    unsigned u = __float_as_uint(x);
    ull r; asm("mov.b64 %0, {%1, %1};" : "=l"(r) : "r"(u)); return r;
}
__device__ __forceinline__ void fma2(ull &d, ull a, ull b){
    asm("fma.rn.f32x2 %0, %1, %2, %0;" : "+l"(d) : "l"(a), "l"(b));
}
__device__ __forceinline__ void unpk(ull v, float &lo, float &hi){
    unsigned ulo, uhi;
    asm("mov.b64 {%0, %1}, %2;" : "=r"(ulo), "=r"(uhi) : "l"(v));
    lo = __uint_as_float(ulo); hi = __uint_as_float(uhi);
}
// bf16 2-term split of (a,b): hi = {bf16(b),bf16(a)}, lo = bf16 residuals
__device__ __forceinline__ void split_pack(float a, float b, unsigned &hi, unsigned &lo){
    unsigned h; asm("cvt.rn.bf16x2.f32 %0, %1, %2;" : "=r"(h) : "f"(b), "f"(a));
    float ra = __uint_as_float(h << 16);
    float rb = __uint_as_float(h & 0xFFFF0000u);
    float la = a - ra, lb = b - rb;
    unsigned l; asm("cvt.rn.bf16x2.f32 %0, %1, %2;" : "=r"(l) : "f"(lb), "f"(la));
    hi = h; lo = l;
}
__device__ __forceinline__ unsigned smem_u32(const void* p){
    unsigned a;
    asm("{ .reg .u64 t; cvta.to.shared.u64 t, %1; cvt.u32.u64 %0, t; }" : "=r"(a) : "l"(p));
    return a;
}
__device__ __forceinline__ void cpa16(unsigned dst, const void* src){
    asm volatile("cp.async.cg.shared.global [%0], [%1], 16;" :: "r"(dst), "l"(src) : "memory");
}
#define CPA_COMMIT() asm volatile("cp.async.commit_group;" ::: "memory")
#define CPA_WAIT1()  asm volatile("cp.async.wait_group 1;" ::: "memory")
#define CPA_WAIT0()  asm volatile("cp.async.wait_group 0;" ::: "memory")

// ---------------- k0a: rule constants + X split (+ zero G/Bc) ----------------
__global__ void k0a_prep(const float* __restrict__ centers, const float* __restrict__ sigmas,
                         const float* __restrict__ X){
    int t = threadIdx.x, blk = blockIdx.x;
    int p = blk*256 + t;
    if (p < NB*128){
        float2 x = *(const float2*)(X + 2*(size_t)p);
        unsigned hi, lo; split_pack(x.x, x.y, hi, lo);
        g_Xhi[p] = hi; g_Xlo[p] = lo;
    }
    if (blk < 128){
        int i = blk*256 + t;
        float sg = sigmas[i];
        float s  = HCONST/(sg*sg) + EPS_C;
        g_S[i]  = s;
        g_CS[i] = centers[i]*s;
    }
    if (blk == 0){
        if (t < OD)          g_G [t]      = 0.f;
        else if (t < 2*OD)   g_Bc[t - OD] = 0.f;
    }
}

__global__ void k0_k2c(const float* __restrict__ centers, const float* __restrict__ sigmas){
    __shared__ float red[64];
    int r = blockIdx.x, tid = threadIdx.x;
    float p = 0.f;
    for (int i = tid; i < IN_D; i += 64){
        float c = centers[i*RU + r], sg = sigmas[i*RU + r];
        float s = HCONST/(sg*sg) + EPS_C;
        p += c*c*s;
    }
    red[tid] = p; __syncthreads();
    for (int s2 = 32; s2 > 0; s2 >>= 1){
        if (tid < s2) red[tid] += red[tid+s2];
        __syncthreads();
    }
    if (tid == 0) g_K2[r] = red[0];
}

// ---------------- k0_tail: tail weights + tail G/Bc ----------------
__global__ void k0_tail(const float* __restrict__ W, const float* __restrict__ gamma,
                        const float* __restrict__ beta){
    __shared__ float rg[4], rb[4];
    int o = blockIdx.x, t = threadIdx.x;
    int d = 32768 + t;
    float wv = W[(size_t)o*DDIM + d];
    float gv = gamma[d]*wv;
    float bv = beta[d]*wv;
    g_Wt[o*RU + t] = gv;
    #pragma unroll
    for (int off = 16; off; off >>= 1){
        gv += __shfl_down_sync(0xffffffffu, gv, off);
        bv += __shfl_down_sync(0xffffffffu, bv, off);
    }
    int lane = t & 31, w = t >> 5;
    if (lane == 0){ rg[w] = gv; rb[w] = bv; }
    __syncthreads();
    if (t == 0){
        atomicAdd(&g_G [o], rg[0]+rg[1]+rg[2]+rg[3]);
        atomicAdd(&g_Bc[o], rb[0]+rb[1]+rb[2]+rb[3]);
    }
}

// ---------------- k0_bsplit: coalesced B build ----------------
__global__ void k0_bsplit(const float* __restrict__ W, const float* __restrict__ gamma,
                          const float* __restrict__ beta){
    __shared__ float gw[128*33];
    __shared__ float rg[8], rb[8];
    const int ic = blockIdx.x, o = blockIdx.y;
    const int t = threadIdx.x, lane = t & 31, w = t >> 5;
    const int i0 = ic*32;
    float sg = 0.f, sb = 0.f;
    #pragma unroll
    for (int u = 0; u < 16; ++u){
        int e = t + u*256;
        int r = e >> 5, il = e & 31;
        int d = r*256 + i0 + il;
        float wv = W[(size_t)o*DDIM + d];
        float gv = gamma[d]*wv;
        gw[r*33 + il] = gv;
        sg += gv; sb += beta[d]*wv;
    }
    __syncthreads();
    #pragma unroll
    for (int u = 0; u < 8; ++u){
        int q = t + u*256;
        int il = q >> 6, rp = q & 63;
        float a = gw[(2*rp  )*33 + il];
        float b = gw[(2*rp+1)*33 + il];
        unsigned hi, lo; split_pack(a, b, hi, lo);
        size_t idx = (size_t)(i0+il)*4096 + o*64 + rp;
        g_Bhi[idx] = hi;
        g_Blo[idx] = lo;
    }
    #pragma unroll
    for (int off = 16; off; off >>= 1){
        sg += __shfl_down_sync(0xffffffffu, sg, off);
        sb += __shfl_down_sync(0xffffffffu, sb, off);
    }
    if (lane == 0){ rg[w] = sg; rb[w] = sb; }
    __syncthreads();
    if (t == 0){
        float a = 0.f, b2 = 0.f;
        #pragma unroll
        for (int u = 0; u < 8; ++u){ a += rg[u]; b2 += rb[u]; }
        atomicAdd(&g_G[o], a); atomicAdd(&g_Bc[o], b2);
    }
}

// ---------------- k1: firing levels + softmax + closed-form LN stats ----------------
__global__ __launch_bounds__(128,4) void k1_frs(const float* __restrict__ X){
    extern __shared__ float sm1[];
    float* Xs = sm1;             // [256][9]
    float* Ss = sm1 + 256*9;     // [32][128]
    float* Cs = Ss  + 32*128;    // [32][128]
    __shared__ float K2s[RU];
    const int tid  = threadIdx.x;
    const int b0   = blockIdx.x * 8;
    const int lane = tid & 31, wg = tid >> 5;
    if (tid < RU) K2s[tid] = g_K2[tid];
    for (int q = tid; q < 8*64; q += 128){
        int bb = q >> 6, i4 = (q & 63)*4;
        float4 v = *(const float4*)(X + (size_t)(b0+bb)*IN_D + i4);
        Xs[(i4+0)*9+bb]=v.x; Xs[(i4+1)*9+bb]=v.y;
        Xs[(i4+2)*9+bb]=v.z; Xs[(i4+3)*9+bb]=v.w;
    }
    ull A1p[2][2], A2p[2][2];
    #pragma unroll
    for (int bi = 0; bi < 2; ++bi){
        A1p[bi][0]=0ull; A1p[bi][1]=0ull; A2p[bi][0]=0ull; A2p[bi][1]=0ull;
    }
    for (int c = 0; c < 8; ++c){
        __syncthreads();
        for (int q = tid; q < 32*32; q += 128){
            int row = q >> 5, col4 = (q & 31)*4;
            *(float4*)(Ss + row*RU + col4) = *(const float4*)(g_S  + (size_t)(c*32+row)*RU + col4);
            *(float4*)(Cs + row*RU + col4) = *(const float4*)(g_CS + (size_t)(c*32+row)*RU + col4);
        }
        __syncthreads();
        #pragma unroll 4
        for (int k = 0; k < 32; ++k){
            int i = c*32 + k;
            float x0 = Xs[i*9 + wg*2 + 0];
            float x1 = Xs[i*9 + wg*2 + 1];
            ull xx0 = pk2(x0*x0), xx1 = pk2(x1*x1);
            ull xp0 = pk2(x0),    xp1 = pk2(x1);
            #pragma unroll
            for (int jp = 0; jp < 2; ++jp){
                ull s2 = *(const ull*)(Ss + k*RU + 2*lane + 64*jp);
                ull c2 = *(const ull*)(Cs + k*RU + 2*lane + 64*jp);
                fma2(A1p[0][jp], xx0, s2); fma2(A1p[1][jp], xx1, s2);
                fma2(A2p[0][jp], xp0, c2); fma2(A2p[1][jp], xp1, c2);
            }
        }
    }
    #pragma unroll
    for (int bi = 0; bi < 2; ++bi){
        float sx = 0.f, sxx = 0.f;
        #pragma unroll
        for (int t = 0; t < 8; ++t){
            float x = Xs[(lane + 32*t)*9 + wg*2 + bi];
            sx += x; sxx += x*x;
        }
        #pragma unroll
        for (int off = 16; off; off >>= 1){
            sx  += __shfl_xor_sync(0xffffffffu, sx,  off);
            sxx += __shfl_xor_sync(0xffffffffu, sxx, off);
        }
        float lg[4], e[4];
        #pragma unroll
        for (int jp = 0; jp < 2; ++jp){
            float a1l,a1h,a2l,a2h;
            unpk(A1p[bi][jp], a1l, a1h);
            unpk(A2p[bi][jp], a2l, a2h);
            int r = 2*lane + 64*jp;
            lg[2*jp+0] = -(a1l - 2.f*a2l + K2s[r+0]) * (1.f/256.f);
            lg[2*jp+1] = -(a1h - 2.f*a2h + K2s[r+1]) * (1.f/256.f);
        }
        float m = fmaxf(fmaxf(lg[0],lg[1]), fmaxf(lg[2],lg[3]));
        #pragma unroll
        for (int off = 16; off; off >>= 1)
            m = fmaxf(m, __shfl_xor_sync(0xffffffffu, m, off));
        float se = 0.f, se2 = 0.f;
        #pragma unroll
        for (int j = 0; j < 4; ++j){ e[j] = __expf(lg[j]-m); se += e[j]; se2 += e[j]*e[j]; }
        #pragma unroll
        for (int off = 16; off; off >>= 1){
            se  += __shfl_xor_sync(0xffffffffu, se,  off);
            se2 += __shfl_xor_sync(0xffffffffu, se2, off);
        }
        float inv  = 1.f/se;
        float mu   = (sx + 1.f) * (1.f/(float)DDIM);
        float ef2  = se2*inv*inv*(sxx + 1.f) * (1.f/(float)DDIM);
        float rstd = rsqrtf(ef2 - mu*mu + LN_EPS_C);
        int b = b0 + wg*2 + bi;
        float fr = inv*rstd;
        #pragma unroll
        for (int jp = 0; jp < 2; ++jp){
            int r = 2*lane + 64*jp;
            g_fsT[(size_t)(r  )*NB + b] = e[2*jp+0]*fr;
            g_fsT[(size_t)(r+1)*NB + b] = e[2*jp+1]*fr;
        }
        if (lane == 0) g_c0[b] = -mu*rstd;
    }
}

// ---------------- k2: bf16 wmma GEMM, 512 thr (4x4 warps), cp.async 2-stage ----------------
#define A_LD 72
#define B_LD 136
#define R_AH 0u
#define R_AL 18432u
#define R_BH 36864u
#define R_BL 54272u
#define BUF_SZ 71680u
#define OFF_WT 143360u
#define OFF_RED 67584u      // partials overlay (after Ps region): 512 floats
#define K2_SMEM 143872u

__global__ __launch_bounds__(512,1) void k2_wmma(const float* __restrict__ bias,
                                                 float* __restrict__ out){
    extern __shared__ __align__(16) char sm[];
    float* Wts = (float*)(sm + OFF_WT);
    float* Ps  = (float*)sm;                 // epilogue overlay [b + r*132]
    float* Red = (float*)(sm + OFF_RED);
    const unsigned base = smem_u32(sm);
    const int tid = threadIdx.x;
    const int b0  = blockIdx.x * 128;
    const int o   = blockIdx.y;
    const int w   = tid >> 5;
    const int mw  = w >> 2, nw = w & 3;      // 4x4 warp grid, 32x32 tiles

    if (tid < 128) Wts[tid] = g_Wt[o*RU + tid];

    auto issue = [&](int kc, unsigned bufb){
        #pragma unroll
        for (int u = 0; u < 2; ++u){
            int q = tid + u*512;             // 1024: A segments
            int row = q >> 3, s = q & 7;
            const unsigned* sh = g_Xhi + (size_t)(b0+row)*128 + kc*32 + s*4;
            const unsigned* sl = g_Xlo + (size_t)(b0+row)*128 + kc*32 + s*4;
            cpa16(bufb + R_AH + row*144 + s*16, sh);
            cpa16(bufb + R_AL + row*144 + s*16, sl);
        }
        #pragma unroll
        for (int u = 0; u < 2; ++u){
            int q = tid + u*512;             // 1024: B segments
            int k = q >> 4, s = q & 15;
            const unsigned* sh = g_Bhi + (size_t)(kc*64+k)*4096 + o*64 + s*4;
            const unsigned* sl = g_Blo + (size_t)(kc*64+k)*4096 + o*64 + s*4;
            cpa16(bufb + R_BH + k*272 + s*16, sh);
            cpa16(bufb + R_BL + k*272 + s*16, sl);
        }
    };

    wmma::fragment<wmma::accumulator,16,16,16,float> acc[2][2];
    #pragma unroll
    for (int mt = 0; mt < 2; ++mt)
        #pragma unroll
        for (int nt = 0; nt < 2; ++nt) wmma::fill_fragment(acc[mt][nt], 0.f);

    issue(0, base); CPA_COMMIT();
    for (int kc = 0; kc < 4; ++kc){
        if (kc + 1 < 4){ issue(kc+1, base + ((kc+1)&1)*BUF_SZ); CPA_COMMIT(); CPA_WAIT1(); }
        else CPA_WAIT0();
        __syncthreads();
        const char* bufc = sm + (kc&1)*BUF_SZ;
        const __nv_bfloat16* Ah = (const __nv_bfloat16*)(bufc + R_AH);
        const __nv_bfloat16* Al = (const __nv_bfloat16*)(bufc + R_AL);
        const __nv_bfloat16* Bh = (const __nv_bfloat16*)(bufc + R_BH);
        const __nv_bfloat16* Bl = (const __nv_bfloat16*)(bufc + R_BL);
        #pragma unroll
        for (int ks = 0; ks < 4; ++ks){
            wmma::fragment<wmma::matrix_a,16,16,16,__nv_bfloat16,wmma::row_major> ah[2], al[2];
            #pragma unroll
            for (int mt = 0; mt < 2; ++mt){
                wmma::load_matrix_sync(ah[mt], Ah + (mw*32 + mt*16)*A_LD + ks*16, A_LD);
                wmma::load_matrix_sync(al[mt], Al + (mw*32 + mt*16)*A_LD + ks*16, A_LD);
            }
            #pragma unroll
            for (int nt = 0; nt < 2; ++nt){
                wmma::fragment<wmma::matrix_b,16,16,16,__nv_bfloat16,wmma::row_major> bh, bl;
                wmma::load_matrix_sync(bh, Bh + ks*16*B_LD + nw*32 + nt*16, B_LD);
                wmma::load_matrix_sync(bl, Bl + ks*16*B_LD + nw*32 + nt*16, B_LD);
                #pragma unroll
                for (int mt = 0; mt < 2; ++mt){
                    wmma::mma_sync(acc[mt][nt], ah[mt], bh, acc[mt][nt]);
                    wmma::mma_sync(acc[mt][nt], ah[mt], bl, acc[mt][nt]);
                    wmma::mma_sync(acc[mt][nt], al[mt], bh, acc[mt][nt]);
                }
            }
        }
        __syncthreads();
    }
    // stage P col-major: element (b_local, r) at Ps[b + r*132]
    #pragma unroll
    for (int mt = 0; mt < 2; ++mt)
        #pragma unroll
        for (int nt = 0; nt < 2; ++nt)
            wmma::store_matrix_sync(Ps + (mw*32 + mt*16) + (size_t)(nw*32 + nt*16)*132,
                                    acc[mt][nt], 132, wmma::mem_col_major);
    __syncthreads();
    {   // rule reduction: 512 threads, each quarter handles 32 r's for one b
        int quad = tid >> 7, bl = tid & 127;
        int b = b0 + bl;
        float s0 = 0.f, s1 = 0.f, s2 = 0.f, s3 = 0.f;
        int rb0 = quad*32;
        #pragma unroll
        for (int u = 0; u < 8; ++u){
            int r = rb0 + 4*u;
            s0 += g_fsT[(size_t)(r  )*NB + b] * (Ps[bl + (r  )*132] + Wts[r  ]);
            s1 += g_fsT[(size_t)(r+1)*NB + b] * (Ps[bl + (r+1)*132] + Wts[r+1]);
            s2 += g_fsT[(size_t)(r+2)*NB + b] * (Ps[bl + (r+2)*132] + Wts[r+2]);
            s3 += g_fsT[(size_t)(r+3)*NB + b] * (Ps[bl + (r+3)*132] + Wts[r+3]);
        }
        Red[tid] = (s0+s1)+(s2+s3);
    }
    __syncthreads();
    if (tid < 128){
        int b = b0 + tid;
        float v = (Red[tid] + Red[tid+128]) + (Red[tid+256] + Red[tid+384]);
        out[(size_t)b*OD + o] = v + g_c0[b]*g_G[o] + g_Bc[o] + bias[o];
    }
}

// ---------------- launch ----------------
extern "C" void kernel_launch(void* const* d_in, const int* in_sizes, int n_in,
                              void* d_out, int out_size){
    const float* X       = (const float*)d_in[0];
    const float* centers = (const float*)d_in[1];
    const float* sigmas  = (const float*)d_in[2];
    const float* gamma   = (const float*)d_in[3];
    const float* beta    = (const float*)d_in[4];
    const float* W       = (const float*)d_in[5];
    const float* bias    = (const float*)d_in[6];
    float* out = (float*)d_out;
    (void)in_sizes; (void)n_in; (void)out_size;

    cudaFuncSetAttribute(k1_frs,  cudaFuncAttributeMaxDynamicSharedMemorySize, 42112);
    cudaFuncSetAttribute(k2_wmma, cudaFuncAttributeMaxDynamicSharedMemorySize, K2_SMEM);

    k0a_prep <<<(NB*128 + 255)/256, 256>>>(centers, sigmas, X);
    k0_k2c   <<<RU, 64>>>(centers, sigmas);
    k0_tail  <<<OD, 128>>>(W, gamma, beta);
    k0_bsplit<<<dim3(8, 64), 256>>>(W, gamma, beta);
    k1_frs   <<<NB/8, 128, 42112>>>(X);
    k2_wmma  <<<dim3(NB/128, OD), 512, K2_SMEM>>>(bias, out);
}

// round 8
// speedup vs baseline: 1.0635x; 1.0635x over previous
#include <cuda_runtime.h>
#include <cuda_bf16.h>
#include <mma.h>

using namespace nvcuda;

#define IN_D 256
#define RU   128
#define OD   64
#define NB   2048
#define DDIM 32896
#define HCONST 0.5f
#define EPS_C  1e-8f
#define LN_EPS_C 1e-5f

typedef unsigned long long ull;

// ---------------- device scratch (allocation-free) ----------------
__device__ float    g_S  [IN_D*RU];
__device__ float    g_CS [IN_D*RU];
__device__ float    g_K2 [RU];
__device__ float    g_G  [OD];
__device__ float    g_Bc [OD];
__device__ float    g_fsT[RU*NB];      // (frs*rstd) transposed: [r][b]
__device__ float    g_c0 [NB];         // -mu*rstd
__device__ float    g_Wt [OD*RU];      // tail weights gamma*W[o][32768+r]
__device__ unsigned g_Bhi[256*4096];   // B hi split [i=256][n_w=4096] bf16x2, n_w = o*64 + r/2
__device__ unsigned g_Blo[256*4096];
__device__ unsigned g_Xhi[NB*128];     // X hi split [b][128 words]
__device__ unsigned g_Xlo[NB*128];

// ---------------- helpers ----------------
__device__ __forceinline__ ull pk2(float x){
    unsigned u = __float_as_uint(x);
    ull r; asm("mov.b64 %0, {%1, %1};" : "=l"(r) : "r"(u)); return r;
}
__device__ __forceinline__ void fma2(ull &d, ull a, ull b){
    asm("fma.rn.f32x2 %0, %1, %2, %0;" : "+l"(d) : "l"(a), "l"(b));
}
__device__ __forceinline__ void unpk(ull v, float &lo, float &hi){
    unsigned ulo, uhi;
    asm("mov.b64 {%0, %1}, %2;" : "=r"(ulo), "=r"(uhi) : "l"(v));
    lo = __uint_as_float(ulo); hi = __uint_as_float(uhi);
}
__device__ __forceinline__ void split_pack(float a, float b, unsigned &hi, unsigned &lo){
    unsigned h; asm("cvt.rn.bf16x2.f32 %0, %1, %2;" : "=r"(h) : "f"(b), "f"(a));
    float ra = __uint_as_float(h << 16);
    float rb = __uint_as_float(h & 0xFFFF0000u);
    float la = a - ra, lb = b - rb;
    unsigned l; asm("cvt.rn.bf16x2.f32 %0, %1, %2;" : "=r"(l) : "f"(lb), "f"(la));
    hi = h; lo = l;
}
__device__ __forceinline__ unsigned smem_u32(const void* p){
    unsigned a;
    asm("{ .reg .u64 t; cvta.to.shared.u64 t, %1; cvt.u32.u64 %0, t; }" : "=r"(a) : "l"(p));
    return a;
}
__device__ __forceinline__ void cpa16(unsigned dst, const void* src){
    asm volatile("cp.async.cg.shared.global [%0], [%1], 16;" :: "r"(dst), "l"(src) : "memory");
}
#define CPA_COMMIT() asm volatile("cp.async.commit_group;" ::: "memory")
#define CPA_WAIT1()  asm volatile("cp.async.wait_group 1;" ::: "memory")
#define CPA_WAIT0()  asm volatile("cp.async.wait_group 0;" ::: "memory")

// ---------------- launch 1: k0a — X split + rule constants + K2 + zero G/Bc ----------------
__global__ void k0a_prep(const float* __restrict__ centers, const float* __restrict__ sigmas,
                         const float* __restrict__ X){
    __shared__ float red[256];
    int t = threadIdx.x, blk = blockIdx.x;
    if (blk < 1024){
        int p = blk*256 + t;
        float2 x = *(const float2*)(X + 2*(size_t)p);
        unsigned hi, lo; split_pack(x.x, x.y, hi, lo);
        g_Xhi[p] = hi; g_Xlo[p] = lo;
        if (blk < 128){
            int i = blk*256 + t;
            float sg = sigmas[i];
            float s  = HCONST/(sg*sg) + EPS_C;
            g_S[i]  = s;
            g_CS[i] = centers[i]*s;
        }
        if (blk == 0){
            if (t < OD)          g_G [t]      = 0.f;
            else if (t < 2*OD)   g_Bc[t - OD] = 0.f;
        }
    } else {
        int r = blk - 1024;      // 128 blocks: K2[r]
        float c = centers[t*RU + r], sg = sigmas[t*RU + r];
        float s = HCONST/(sg*sg) + EPS_C;
        red[t] = c*c*s;
        __syncthreads();
        for (int s2 = 128; s2 > 0; s2 >>= 1){
            if (t < s2) red[t] += red[t+s2];
            __syncthreads();
        }
        if (t == 0) g_K2[r] = red[0];
    }
}

// ---------------- launch 2: k0_bsplit — coalesced B build (+ tail fused at ic==7) ----------------
__global__ void k0_bsplit(const float* __restrict__ W, const float* __restrict__ gamma,
                          const float* __restrict__ beta){
    __shared__ float gw[128*33];
    __shared__ float rg[8], rb[8], trg[4], trb[4];
    const int ic = blockIdx.x, o = blockIdx.y;
    const int t = threadIdx.x, lane = t & 31, w = t >> 5;
    const int i0 = ic*32;
    float sg = 0.f, sb = 0.f;
    #pragma unroll
    for (int u = 0; u < 16; ++u){
        int e = t + u*256;
        int r = e >> 5, il = e & 31;
        int d = r*256 + i0 + il;
        float wv = W[(size_t)o*DDIM + d];
        float gv = gamma[d]*wv;
        gw[r*33 + il] = gv;
        sg += gv; sb += beta[d]*wv;
    }
    __syncthreads();
    #pragma unroll
    for (int u = 0; u < 8; ++u){
        int q = t + u*256;
        int il = q >> 6, rp = q & 63;
        float a = gw[(2*rp  )*33 + il];
        float b = gw[(2*rp+1)*33 + il];
        unsigned hi, lo; split_pack(a, b, hi, lo);
        size_t idx = (size_t)(i0+il)*4096 + o*64 + rp;
        g_Bhi[idx] = hi;
        g_Blo[idx] = lo;
    }
    #pragma unroll
    for (int off = 16; off; off >>= 1){
        sg += __shfl_down_sync(0xffffffffu, sg, off);
        sb += __shfl_down_sync(0xffffffffu, sb, off);
    }
    if (lane == 0){ rg[w] = sg; rb[w] = sb; }
    __syncthreads();
    if (t == 0){
        float a = 0.f, b2 = 0.f;
        #pragma unroll
        for (int u = 0; u < 8; ++u){ a += rg[u]; b2 += rb[u]; }
        atomicAdd(&g_G[o], a); atomicAdd(&g_Bc[o], b2);
    }
    // fused tail (one ic per o)
    if (ic == 7){
        float tgv = 0.f, tbv = 0.f;
        if (t < 128){
            int d = 32768 + t;
            float wv = W[(size_t)o*DDIM + d];
            tgv = gamma[d]*wv;
            tbv = beta[d]*wv;
            g_Wt[o*RU + t] = tgv;
        }
        #pragma unroll
        for (int off = 16; off; off >>= 1){
            tgv += __shfl_down_sync(0xffffffffu, tgv, off);
            tbv += __shfl_down_sync(0xffffffffu, tbv, off);
        }
        if (lane == 0 && t < 128){ trg[w] = tgv; trb[w] = tbv; }
        __syncthreads();
        if (t == 0){
            atomicAdd(&g_G [o], trg[0]+trg[1]+trg[2]+trg[3]);
            atomicAdd(&g_Bc[o], trb[0]+trb[1]+trb[2]+trb[3]);
        }
    }
}

// ---------------- launch 3: k1 — firing levels + softmax + closed-form LN stats ----------------
__global__ __launch_bounds__(128,4) void k1_frs(const float* __restrict__ X){
    extern __shared__ float sm1[];
    float* Xs = sm1;             // [256][9]
    float* Ss = sm1 + 256*9;     // [32][128]
    float* Cs = Ss  + 32*128;    // [32][128]
    __shared__ float K2s[RU];
    const int tid  = threadIdx.x;
    const int b0   = blockIdx.x * 8;
    const int lane = tid & 31, wg = tid >> 5;
    if (tid < RU) K2s[tid] = g_K2[tid];
    for (int q = tid; q < 8*64; q += 128){
        int bb = q >> 6, i4 = (q & 63)*4;
        float4 v = *(const float4*)(X + (size_t)(b0+bb)*IN_D + i4);
        Xs[(i4+0)*9+bb]=v.x; Xs[(i4+1)*9+bb]=v.y;
        Xs[(i4+2)*9+bb]=v.z; Xs[(i4+3)*9+bb]=v.w;
    }
    ull A1p[2][2], A2p[2][2];
    #pragma unroll
    for (int bi = 0; bi < 2; ++bi){
        A1p[bi][0]=0ull; A1p[bi][1]=0ull; A2p[bi][0]=0ull; A2p[bi][1]=0ull;
    }
    for (int c = 0; c < 8; ++c){
        __syncthreads();
        for (int q = tid; q < 32*32; q += 128){
            int row = q >> 5, col4 = (q & 31)*4;
            *(float4*)(Ss + row*RU + col4) = *(const float4*)(g_S  + (size_t)(c*32+row)*RU + col4);
            *(float4*)(Cs + row*RU + col4) = *(const float4*)(g_CS + (size_t)(c*32+row)*RU + col4);
        }
        __syncthreads();
        #pragma unroll 4
        for (int k = 0; k < 32; ++k){
            int i = c*32 + k;
            float x0 = Xs[i*9 + wg*2 + 0];
            float x1 = Xs[i*9 + wg*2 + 1];
            ull xx0 = pk2(x0*x0), xx1 = pk2(x1*x1);
            ull xp0 = pk2(x0),    xp1 = pk2(x1);
            #pragma unroll
            for (int jp = 0; jp < 2; ++jp){
                ull s2 = *(const ull*)(Ss + k*RU + 2*lane + 64*jp);
                ull c2 = *(const ull*)(Cs + k*RU + 2*lane + 64*jp);
                fma2(A1p[0][jp], xx0, s2); fma2(A1p[1][jp], xx1, s2);
                fma2(A2p[0][jp], xp0, c2); fma2(A2p[1][jp], xp1, c2);
            }
        }
    }
    #pragma unroll
    for (int bi = 0; bi < 2; ++bi){
        float sx = 0.f, sxx = 0.f;
        #pragma unroll
        for (int t = 0; t < 8; ++t){
            float x = Xs[(lane + 32*t)*9 + wg*2 + bi];
            sx += x; sxx += x*x;
        }
        #pragma unroll
        for (int off = 16; off; off >>= 1){
            sx  += __shfl_xor_sync(0xffffffffu, sx,  off);
            sxx += __shfl_xor_sync(0xffffffffu, sxx, off);
        }
        float lg[4], e[4];
        #pragma unroll
        for (int jp = 0; jp < 2; ++jp){
            float a1l,a1h,a2l,a2h;
            unpk(A1p[bi][jp], a1l, a1h);
            unpk(A2p[bi][jp], a2l, a2h);
            int r = 2*lane + 64*jp;
            lg[2*jp+0] = -(a1l - 2.f*a2l + K2s[r+0]) * (1.f/256.f);
            lg[2*jp+1] = -(a1h - 2.f*a2h + K2s[r+1]) * (1.f/256.f);
        }
        float m = fmaxf(fmaxf(lg[0],lg[1]), fmaxf(lg[2],lg[3]));
        #pragma unroll
        for (int off = 16; off; off >>= 1)
            m = fmaxf(m, __shfl_xor_sync(0xffffffffu, m, off));
        float se = 0.f, se2 = 0.f;
        #pragma unroll
        for (int j = 0; j < 4; ++j){ e[j] = __expf(lg[j]-m); se += e[j]; se2 += e[j]*e[j]; }
        #pragma unroll
        for (int off = 16; off; off >>= 1){
            se  += __shfl_xor_sync(0xffffffffu, se,  off);
            se2 += __shfl_xor_sync(0xffffffffu, se2, off);
        }
        float inv  = 1.f/se;
        float mu   = (sx + 1.f) * (1.f/(float)DDIM);
        float ef2  = se2*inv*inv*(sxx + 1.f) * (1.f/(float)DDIM);
        float rstd = rsqrtf(ef2 - mu*mu + LN_EPS_C);
        int b = b0 + wg*2 + bi;
        float fr = inv*rstd;
        #pragma unroll
        for (int jp = 0; jp < 2; ++jp){
            int r = 2*lane + 64*jp;
            g_fsT[(size_t)(r  )*NB + b] = e[2*jp+0]*fr;
            g_fsT[(size_t)(r+1)*NB + b] = e[2*jp+1]*fr;
        }
        if (lane == 0) g_c0[b] = -mu*rstd;
    }
}

// ---------------- launch 4: k2 — bf16 wmma GEMM, M=128 x N=256 (2 o's), cp.async 2-stage ----------------
#define A_LD 72
#define B_LD 264
#define R_AH 0u
#define R_AL 18432u
#define R_BH 36864u
#define R_BL 70656u
#define BUF_SZ 104448u
#define OFF_WT 208896u
#define OFF_RED 135168u     // after Ps region (256*132*4)
#define K2_SMEM 209920u

__global__ __launch_bounds__(512,1) void k2_wmma(const float* __restrict__ bias,
                                                 float* __restrict__ out){
    extern __shared__ __align__(16) char sm[];
    float* Wts = (float*)(sm + OFF_WT);
    float* Ps  = (float*)sm;                 // epilogue overlay [bl + r*132], r in [0,256)
    float* Red = (float*)(sm + OFF_RED);
    const unsigned base = smem_u32(sm);
    const int tid = threadIdx.x;
    const int b0  = blockIdx.x * 128;
    const int o0  = blockIdx.y * 2;
    const int w   = tid >> 5;
    const int mw  = w >> 2, nw = w & 3;      // 4x4 warps, 32(m) x 64(n) tiles

    if (tid < 256) Wts[tid] = g_Wt[(o0 + (tid>>7))*RU + (tid & 127)];

    auto issue = [&](int kc, unsigned bufb){
        #pragma unroll
        for (int u = 0; u < 2; ++u){
            int q = tid + u*512;             // 1024: A rows x segs
            int row = q >> 3, s = q & 7;
            const unsigned* sh = g_Xhi + (size_t)(b0+row)*128 + kc*32 + s*4;
            const unsigned* sl = g_Xlo + (size_t)(b0+row)*128 + kc*32 + s*4;
            cpa16(bufb + R_AH + row*144 + s*16, sh);
            cpa16(bufb + R_AL + row*144 + s*16, sl);
        }
        #pragma unroll
        for (int u = 0; u < 4; ++u){
            int q = tid + u*512;             // 2048: B rows x segs (128 words = 512B per row)
            int k = q >> 5, s = q & 31;
            const unsigned* sh = g_Bhi + (size_t)(kc*64+k)*4096 + o0*64 + s*4;
            const unsigned* sl = g_Blo + (size_t)(kc*64+k)*4096 + o0*64 + s*4;
            cpa16(bufb + R_BH + k*528 + s*16, sh);
            cpa16(bufb + R_BL + k*528 + s*16, sl);
        }
    };

    wmma::fragment<wmma::accumulator,16,16,16,float> acc[2][4];
    #pragma unroll
    for (int mt = 0; mt < 2; ++mt)
        #pragma unroll
        for (int nt = 0; nt < 4; ++nt) wmma::fill_fragment(acc[mt][nt], 0.f);

    issue(0, base); CPA_COMMIT();
    for (int kc = 0; kc < 4; ++kc){
        if (kc + 1 < 4){ issue(kc+1, base + ((kc+1)&1)*BUF_SZ); CPA_COMMIT(); CPA_WAIT1(); }
        else CPA_WAIT0();
        __syncthreads();
        const char* bufc = sm + (kc&1)*BUF_SZ;
        const __nv_bfloat16* Ah = (const __nv_bfloat16*)(bufc + R_AH);
        const __nv_bfloat16* Al = (const __nv_bfloat16*)(bufc + R_AL);
        const __nv_bfloat16* Bh = (const __nv_bfloat16*)(bufc + R_BH);
        const __nv_bfloat16* Bl = (const __nv_bfloat16*)(bufc + R_BL);
        #pragma unroll
        for (int ks = 0; ks < 4; ++ks){
            wmma::fragment<wmma::matrix_a,16,16,16,__nv_bfloat16,wmma::row_major> ah[2], al[2];
            #pragma unroll
            for (int mt = 0; mt < 2; ++mt){
                wmma::load_matrix_sync(ah[mt], Ah + (mw*32 + mt*16)*A_LD + ks*16, A_LD);
                wmma::load_matrix_sync(al[mt], Al + (mw*32 + mt*16)*A_LD + ks*16, A_LD);
            }
            #pragma unroll
            for (int nt = 0; nt < 4; ++nt){
                wmma::fragment<wmma::matrix_b,16,16,16,__nv_bfloat16,wmma::row_major> bh, bl;
                wmma::load_matrix_sync(bh, Bh + ks*16*B_LD + nw*64 + nt*16, B_LD);
                wmma::load_matrix_sync(bl, Bl + ks*16*B_LD + nw*64 + nt*16, B_LD);
                #pragma unroll
                for (int mt = 0; mt < 2; ++mt){
                    wmma::mma_sync(acc[mt][nt], ah[mt], bh, acc[mt][nt]);
                    wmma::mma_sync(acc[mt][nt], ah[mt], bl, acc[mt][nt]);
                    wmma::mma_sync(acc[mt][nt], al[mt], bh, acc[mt][nt]);
                }
            }
        }
        __syncthreads();
    }
    // stage P col-major: element (b_local, n) at Ps[bl + n*132], n = ol*128 + rule
    #pragma unroll
    for (int mt = 0; mt < 2; ++mt)
        #pragma unroll
        for (int nt = 0; nt < 4; ++nt)
            wmma::store_matrix_sync(Ps + (mw*32 + mt*16) + (size_t)(nw*64 + nt*16)*132,
                                    acc[mt][nt], 132, wmma::mem_col_major);
    __syncthreads();
    {   // rule reduction: quad = (ol, r-half); 64 rules each
        int quad = tid >> 7, bl = tid & 127;
        int ol = quad >> 1, rh = quad & 1;
        int b = b0 + bl;
        float s0 = 0.f, s1 = 0.f, s2 = 0.f, s3 = 0.f;
        #pragma unroll
        for (int u = 0; u < 16; ++u){
            int rule = rh*64 + 4*u;
            int n = ol*128 + rule;
            s0 += g_fsT[(size_t)(rule  )*NB + b] * (Ps[bl + (n  )*132] + Wts[n  ]);
            s1 += g_fsT[(size_t)(rule+1)*NB + b] * (Ps[bl + (n+1)*132] + Wts[n+1]);
            s2 += g_fsT[(size_t)(rule+2)*NB + b] * (Ps[bl + (n+2)*132] + Wts[n+2]);
            s3 += g_fsT[(size_t)(rule+3)*NB + b] * (Ps[bl + (n+3)*132] + Wts[n+3]);
        }
        Red[quad*128 + bl] = (s0+s1)+(s2+s3);
    }
    __syncthreads();
    if (tid < 256){
        int ol = tid >> 7, bl = tid & 127;
        int b = b0 + bl, o = o0 + ol;
        float v = Red[(ol*2)*128 + bl] + Red[(ol*2+1)*128 + bl];
        out[(size_t)b*OD + o] = v + g_c0[b]*g_G[o] + g_Bc[o] + bias[o];
    }
}

// ---------------- launch ----------------
extern "C" void kernel_launch(void* const* d_in, const int* in_sizes, int n_in,
                              void* d_out, int out_size){
    const float* X       = (const float*)d_in[0];
    const float* centers = (const float*)d_in[1];
    const float* sigmas  = (const float*)d_in[2];
    const float* gamma   = (const float*)d_in[3];
    const float* beta    = (const float*)d_in[4];
    const float* W       = (const float*)d_in[5];
    const float* bias    = (const float*)d_in[6];
    float* out = (float*)d_out;
    (void)in_sizes; (void)n_in; (void)out_size;

    cudaFuncSetAttribute(k1_frs,  cudaFuncAttributeMaxDynamicSharedMemorySize, 42112);
    cudaFuncSetAttribute(k2_wmma, cudaFuncAttributeMaxDynamicSharedMemorySize, K2_SMEM);

    k0a_prep <<<1152, 256>>>(centers, sigmas, X);          // 1
    k0_bsplit<<<dim3(8, 64), 256>>>(W, gamma, beta);       // 2
    k1_frs   <<<NB/8, 128, 42112>>>(X);                    // 3
    k2_wmma  <<<dim3(NB/128, OD/2), 512, K2_SMEM>>>(bias, out);  // 4 (profiled)
}

// round 11
// speedup vs baseline: 1.1494x; 1.0808x over previous
#include <cuda_runtime.h>
#include <cuda_bf16.h>
#include <mma.h>

using namespace nvcuda;

#define IN_D 256
#define RU   128
#define OD   64
#define NB   2048
#define DDIM 32896
#define HCONST 0.5f
#define EPS_C  1e-8f
#define LN_EPS_C 1e-5f

typedef unsigned long long ull;

// ---------------- device scratch (allocation-free) ----------------
__device__ float    g_S  [IN_D*RU];
__device__ float    g_CS [IN_D*RU];
__device__ float    g_K2 [RU];
__device__ float    g_G  [OD];
__device__ float    g_Bc [OD];
__device__ float    g_fsT[RU*NB];      // (frs*rstd) transposed: [r][b]
__device__ float    g_c0 [NB];         // -mu*rstd
__device__ float    g_Wt [OD*RU];      // tail weights gamma*W[o][32768+r]
__device__ unsigned g_Bhi[256*4096];   // B hi split [i=256][n_w=4096] bf16x2, n_w = o*64 + r/2
__device__ unsigned g_Blo[256*4096];
__device__ unsigned g_Xhi[NB*128];     // X hi split [b][128 words]
__device__ unsigned g_Xlo[NB*128];

// ---------------- helpers ----------------
__device__ __forceinline__ ull pk2(float x){
    unsigned u = __float_as_uint(x);
    ull r; asm("mov.b64 %0, {%1, %1};" : "=l"(r) : "r"(u)); return r;
}
__device__ __forceinline__ void fma2(ull &d, ull a, ull b){
    asm("fma.rn.f32x2 %0, %1, %2, %0;" : "+l"(d) : "l"(a), "l"(b));
}
__device__ __forceinline__ void unpk(ull v, float &lo, float &hi){
    unsigned ulo, uhi;
    asm("mov.b64 {%0, %1}, %2;" : "=r"(ulo), "=r"(uhi) : "l"(v));
    lo = __uint_as_float(ulo); hi = __uint_as_float(uhi);
}
__device__ __forceinline__ void split_pack(float a, float b, unsigned &hi, unsigned &lo){
    unsigned h; asm("cvt.rn.bf16x2.f32 %0, %1, %2;" : "=r"(h) : "f"(b), "f"(a));
    float ra = __uint_as_float(h << 16);
    float rb = __uint_as_float(h & 0xFFFF0000u);
    float la = a - ra, lb = b - rb;
    unsigned l; asm("cvt.rn.bf16x2.f32 %0, %1, %2;" : "=r"(l) : "f"(lb), "f"(la));
    hi = h; lo = l;
}
__device__ __forceinline__ unsigned smem_u32(const void* p){
    unsigned a;
    asm("{ .reg .u64 t; cvta.to.shared.u64 t, %1; cvt.u32.u64 %0, t; }" : "=r"(a) : "l"(p));
    return a;
}
__device__ __forceinline__ void cpa16(unsigned dst, const void* src){
    asm volatile("cp.async.cg.shared.global [%0], [%1], 16;" :: "r"(dst), "l"(src) : "memory");
}
#define CPA_COMMIT() asm volatile("cp.async.commit_group;" ::: "memory")
#define CPA_WAIT1()  asm volatile("cp.async.wait_group 1;" ::: "memory")
#define CPA_WAIT0()  asm volatile("cp.async.wait_group 0;" ::: "memory")

// ---------------- launch 1: k0a — X split + rule constants + K2 + zero G/Bc ----------------
__global__ void k0a_prep(const float* __restrict__ centers, const float* __restrict__ sigmas,
                         const float* __restrict__ X){
    __shared__ float red[256];
    int t = threadIdx.x, blk = blockIdx.x;
    if (blk < 1024){
        int p = blk*256 + t;
        float2 x = *(const float2*)(X + 2*(size_t)p);
        unsigned hi, lo; split_pack(x.x, x.y, hi, lo);
        g_Xhi[p] = hi; g_Xlo[p] = lo;
        if (blk < 128){
            int i = blk*256 + t;
            float sg = sigmas[i];
            float s  = HCONST/(sg*sg) + EPS_C;
            g_S[i]  = s;
            g_CS[i] = centers[i]*s;
        }
        if (blk == 0){
            if (t < OD)          g_G [t]      = 0.f;
            else if (t < 2*OD)   g_Bc[t - OD] = 0.f;
        }
    } else {
        int r = blk - 1024;      // 128 blocks: K2[r]
        float c = centers[t*RU + r], sg = sigmas[t*RU + r];
        float s = HCONST/(sg*sg) + EPS_C;
        red[t] = c*c*s;
        __syncthreads();
        for (int s2 = 128; s2 > 0; s2 >>= 1){
            if (t < s2) red[t] += red[t+s2];
            __syncthreads();
        }
        if (t == 0) g_K2[r] = red[0];
    }
}

// ---------------- launch 2: k0_bsplit — coalesced B build (+ tail fused at ic==7) ----------------
__global__ void k0_bsplit(const float* __restrict__ W, const float* __restrict__ gamma,
                          const float* __restrict__ beta){
    __shared__ float gw[128*33];
    __shared__ float rg[8], rb[8], trg[4], trb[4];
    const int ic = blockIdx.x, o = blockIdx.y;
    const int t = threadIdx.x, lane = t & 31, w = t >> 5;
    const int i0 = ic*32;
    float sg = 0.f, sb = 0.f;
    #pragma unroll
    for (int u = 0; u < 16; ++u){
        int e = t + u*256;
        int r = e >> 5, il = e & 31;
        int d = r*256 + i0 + il;
        float wv = W[(size_t)o*DDIM + d];
        float gv = gamma[d]*wv;
        gw[r*33 + il] = gv;
        sg += gv; sb += beta[d]*wv;
    }
    __syncthreads();
    #pragma unroll
    for (int u = 0; u < 8; ++u){
        int q = t + u*256;
        int il = q >> 6, rp = q & 63;
        float a = gw[(2*rp  )*33 + il];
        float b = gw[(2*rp+1)*33 + il];
        unsigned hi, lo; split_pack(a, b, hi, lo);
        size_t idx = (size_t)(i0+il)*4096 + o*64 + rp;
        g_Bhi[idx] = hi;
        g_Blo[idx] = lo;
    }
    #pragma unroll
    for (int off = 16; off; off >>= 1){
        sg += __shfl_down_sync(0xffffffffu, sg, off);
        sb += __shfl_down_sync(0xffffffffu, sb, off);
    }
    if (lane == 0){ rg[w] = sg; rb[w] = sb; }
    __syncthreads();
    if (t == 0){
        float a = 0.f, b2 = 0.f;
        #pragma unroll
        for (int u = 0; u < 8; ++u){ a += rg[u]; b2 += rb[u]; }
        atomicAdd(&g_G[o], a); atomicAdd(&g_Bc[o], b2);
    }
    if (ic == 7){
        float tgv = 0.f, tbv = 0.f;
        if (t < 128){
            int d = 32768 + t;
            float wv = W[(size_t)o*DDIM + d];
            tgv = gamma[d]*wv;
            tbv = beta[d]*wv;
            g_Wt[o*RU + t] = tgv;
        }
        #pragma unroll
        for (int off = 16; off; off >>= 1){
            tgv += __shfl_down_sync(0xffffffffu, tgv, off);
            tbv += __shfl_down_sync(0xffffffffu, tbv, off);
        }
        if (lane == 0 && t < 128){ trg[w] = tgv; trb[w] = tbv; }
        __syncthreads();
        if (t == 0){
            atomicAdd(&g_G [o], trg[0]+trg[1]+trg[2]+trg[3]);
            atomicAdd(&g_Bc[o], trb[0]+trb[1]+trb[2]+trb[3]);
        }
    }
}

// ---------------- launch 3: k1 — firing levels + softmax + closed-form LN stats ----------------
__global__ __launch_bounds__(128,4) void k1_frs(const float* __restrict__ X){
    extern __shared__ float sm1[];
    float* Xs = sm1;             // [256][9]
    float* Ss = sm1 + 256*9;     // [32][128]
    float* Cs = Ss  + 32*128;    // [32][128]
    __shared__ float K2s[RU];
    const int tid  = threadIdx.x;
    const int b0   = blockIdx.x * 8;
    const int lane = tid & 31, wg = tid >> 5;
    if (tid < RU) K2s[tid] = g_K2[tid];
    for (int q = tid; q < 8*64; q += 128){
        int bb = q >> 6, i4 = (q & 63)*4;
        float4 v = *(const float4*)(X + (size_t)(b0+bb)*IN_D + i4);
        Xs[(i4+0)*9+bb]=v.x; Xs[(i4+1)*9+bb]=v.y;
        Xs[(i4+2)*9+bb]=v.z; Xs[(i4+3)*9+bb]=v.w;
    }
    ull A1p[2][2], A2p[2][2];
    #pragma unroll
    for (int bi = 0; bi < 2; ++bi){
        A1p[bi][0]=0ull; A1p[bi][1]=0ull; A2p[bi][0]=0ull; A2p[bi][1]=0ull;
    }
    for (int c = 0; c < 8; ++c){
        __syncthreads();
        for (int q = tid; q < 32*32; q += 128){
            int row = q >> 5, col4 = (q & 31)*4;
            *(float4*)(Ss + row*RU + col4) = *(const float4*)(g_S  + (size_t)(c*32+row)*RU + col4);
            *(float4*)(Cs + row*RU + col4) = *(const float4*)(g_CS + (size_t)(c*32+row)*RU + col4);
        }
        __syncthreads();
        #pragma unroll 4
        for (int k = 0; k < 32; ++k){
            int i = c*32 + k;
            float x0 = Xs[i*9 + wg*2 + 0];
            float x1 = Xs[i*9 + wg*2 + 1];
            ull xx0 = pk2(x0*x0), xx1 = pk2(x1*x1);
            ull xp0 = pk2(x0),    xp1 = pk2(x1);
            #pragma unroll
            for (int jp = 0; jp < 2; ++jp){
                ull s2 = *(const ull*)(Ss + k*RU + 2*lane + 64*jp);
                ull c2 = *(const ull*)(Cs + k*RU + 2*lane + 64*jp);
                fma2(A1p[0][jp], xx0, s2); fma2(A1p[1][jp], xx1, s2);
                fma2(A2p[0][jp], xp0, c2); fma2(A2p[1][jp], xp1, c2);
            }
        }
    }
    #pragma unroll
    for (int bi = 0; bi < 2; ++bi){
        float sx = 0.f, sxx = 0.f;
        #pragma unroll
        for (int t = 0; t < 8; ++t){
            float x = Xs[(lane + 32*t)*9 + wg*2 + bi];
            sx += x; sxx += x*x;
        }
        #pragma unroll
        for (int off = 16; off; off >>= 1){
            sx  += __shfl_xor_sync(0xffffffffu, sx,  off);
            sxx += __shfl_xor_sync(0xffffffffu, sxx, off);
        }
        float lg[4], e[4];
        #pragma unroll
        for (int jp = 0; jp < 2; ++jp){
            float a1l,a1h,a2l,a2h;
            unpk(A1p[bi][jp], a1l, a1h);
            unpk(A2p[bi][jp], a2l, a2h);
            int r = 2*lane + 64*jp;
            lg[2*jp+0] = -(a1l - 2.f*a2l + K2s[r+0]) * (1.f/256.f);
            lg[2*jp+1] = -(a1h - 2.f*a2h + K2s[r+1]) * (1.f/256.f);
        }
        float m = fmaxf(fmaxf(lg[0],lg[1]), fmaxf(lg[2],lg[3]));
        #pragma unroll
        for (int off = 16; off; off >>= 1)
            m = fmaxf(m, __shfl_xor_sync(0xffffffffu, m, off));
        float se = 0.f, se2 = 0.f;
        #pragma unroll
        for (int j = 0; j < 4; ++j){ e[j] = __expf(lg[j]-m); se += e[j]; se2 += e[j]*e[j]; }
        #pragma unroll
        for (int off = 16; off; off >>= 1){
            se  += __shfl_xor_sync(0xffffffffu, se,  off);
            se2 += __shfl_xor_sync(0xffffffffu, se2, off);
        }
        float inv  = 1.f/se;
        float mu   = (sx + 1.f) * (1.f/(float)DDIM);
        float ef2  = se2*inv*inv*(sxx + 1.f) * (1.f/(float)DDIM);
        float rstd = rsqrtf(ef2 - mu*mu + LN_EPS_C);
        int b = b0 + wg*2 + bi;
        float fr = inv*rstd;
        #pragma unroll
        for (int jp = 0; jp < 2; ++jp){
            int r = 2*lane + 64*jp;
            g_fsT[(size_t)(r  )*NB + b] = e[2*jp+0]*fr;
            g_fsT[(size_t)(r+1)*NB + b] = e[2*jp+1]*fr;
        }
        if (lane == 0) g_c0[b] = -mu*rstd;
    }
}

// ---------------- launch 4: k2 — bf16 wmma GEMM, M=128 x N=128, 256 thr, 2 CTAs/SM ----------------
// K-chunks of 32 (8 chunks), 2-stage cp.async. Warp grid 4x2, per-warp tile 32m x 64n.
// Row pitches are 16B multiples: A 80B (40 el), B 272B (136 el).
#define A_LDE 40          // A row pitch in bf16 elements (80B = 16*5)
#define B_LDE 136         // B row pitch in bf16 elements (272B = 16*17)
#define R_AH 0u
#define R_AL 10240u
#define R_BH 20480u
#define R_BL 29184u
#define BUF_SZ 37888u
#define OFF_RED 75776u    // 256 floats
#define OFF_WT  76800u    // 128 floats
#define K2_SMEM 77312u

__global__ __launch_bounds__(256,2) void k2_wmma(const float* __restrict__ bias,
                                                 float* __restrict__ out){
    extern __shared__ __align__(16) char sm[];
    float* Wts = (float*)(sm + OFF_WT);
    float* Ps  = (float*)sm;                 // epilogue overlay [bl + n*132], n in [0,128)
    float* Red = (float*)(sm + OFF_RED);
    const unsigned base = smem_u32(sm);
    const int tid = threadIdx.x;
    const int b0  = blockIdx.x * 128;
    const int o   = blockIdx.y;
    const int w   = tid >> 5;
    const int mw  = w >> 1, nw = w & 1;      // 4x2 warps: 32m x 64n tiles

    if (tid < 128) Wts[tid] = g_Wt[o*RU + tid];

    auto issue = [&](int kc, unsigned bufb){
        #pragma unroll
        for (int u = 0; u < 2; ++u){
            int q = tid + u*256;             // 512: A 128 rows x 4 segs (16 words/row per chunk)
            int row = q >> 2, s = q & 3;
            const unsigned* sh = g_Xhi + (size_t)(b0+row)*128 + kc*16 + s*4;
            const unsigned* sl = g_Xlo + (size_t)(b0+row)*128 + kc*16 + s*4;
            cpa16(bufb + R_AH + row*80 + s*16, sh);
            cpa16(bufb + R_AL + row*80 + s*16, sl);
        }
        #pragma unroll
        for (int u = 0; u < 2; ++u){
            int q = tid + u*256;             // 512: B 32 rows x 16 segs (64 words/row)
            int k = q >> 4, s = q & 15;
            const unsigned* sh = g_Bhi + (size_t)(kc*32+k)*4096 + o*64 + s*4;
            const unsigned* sl = g_Blo + (size_t)(kc*32+k)*4096 + o*64 + s*4;
            cpa16(bufb + R_BH + k*272 + s*16, sh);
            cpa16(bufb + R_BL + k*272 + s*16, sl);
        }
    };

    wmma::fragment<wmma::accumulator,16,16,16,float> acc[2][4];
    #pragma unroll
    for (int mt = 0; mt < 2; ++mt)
        #pragma unroll
        for (int nt = 0; nt < 4; ++nt) wmma::fill_fragment(acc[mt][nt], 0.f);

    issue(0, base); CPA_COMMIT();
    for (int kc = 0; kc < 8; ++kc){
        if (kc + 1 < 8){ issue(kc+1, base + ((kc+1)&1)*BUF_SZ); CPA_COMMIT(); CPA_WAIT1(); }
        else CPA_WAIT0();
        __syncthreads();
        const char* bufc = sm + (kc&1)*BUF_SZ;
        const __nv_bfloat16* Ah = (const __nv_bfloat16*)(bufc + R_AH);
        const __nv_bfloat16* Al = (const __nv_bfloat16*)(bufc + R_AL);
        const __nv_bfloat16* Bh = (const __nv_bfloat16*)(bufc + R_BH);
        const __nv_bfloat16* Bl = (const __nv_bfloat16*)(bufc + R_BL);
        #pragma unroll
        for (int ks = 0; ks < 2; ++ks){
            wmma::fragment<wmma::matrix_a,16,16,16,__nv_bfloat16,wmma::row_major> ah[2], al[2];
            #pragma unroll
            for (int mt = 0; mt < 2; ++mt){
                wmma::load_matrix_sync(ah[mt], Ah + (mw*32 + mt*16)*A_LDE + ks*16, A_LDE);
                wmma::load_matrix_sync(al[mt], Al + (mw*32 + mt*16)*A_LDE + ks*16, A_LDE);
            }
            #pragma unroll
            for (int nt = 0; nt < 4; ++nt){
                wmma::fragment<wmma::matrix_b,16,16,16,__nv_bfloat16,wmma::row_major> bh, bl;
                wmma::load_matrix_sync(bh, Bh + ks*16*B_LDE + nw*64 + nt*16, B_LDE);
                wmma::load_matrix_sync(bl, Bl + ks*16*B_LDE + nw*64 + nt*16, B_LDE);
                #pragma unroll
                for (int mt = 0; mt < 2; ++mt){
                    wmma::mma_sync(acc[mt][nt], ah[mt], bh, acc[mt][nt]);
                    wmma::mma_sync(acc[mt][nt], ah[mt], bl, acc[mt][nt]);
                    wmma::mma_sync(acc[mt][nt], al[mt], bh, acc[mt][nt]);
                }
            }
        }
        __syncthreads();
    }
    // stage P col-major: element (b_local, n) at Ps[bl + n*132]
    #pragma unroll
    for (int mt = 0; mt < 2; ++mt)
        #pragma unroll
        for (int nt = 0; nt < 4; ++nt)
            wmma::store_matrix_sync(Ps + (mw*32 + mt*16) + (size_t)(nw*64 + nt*16)*132,
                                    acc[mt][nt], 132, wmma::mem_col_major);
    __syncthreads();
    {   // rule reduction: 2 halves x 128 b, 64 rules each
        int half = tid >> 7, bl = tid & 127;
        int b = b0 + bl;
        float s0 = 0.f, s1 = 0.f, s2 = 0.f, s3 = 0.f;
        int rb0 = half*64;
        #pragma unroll
        for (int u = 0; u < 16; ++u){
            int r = rb0 + 4*u;
            s0 += g_fsT[(size_t)(r  )*NB + b] * (Ps[bl + (r  )*132] + Wts[r  ]);
            s1 += g_fsT[(size_t)(r+1)*NB + b] * (Ps[bl + (r+1)*132] + Wts[r+1]);
            s2 += g_fsT[(size_t)(r+2)*NB + b] * (Ps[bl + (r+2)*132] + Wts[r+2]);
            s3 += g_fsT[(size_t)(r+3)*NB + b] * (Ps[bl + (r+3)*132] + Wts[r+3]);
        }
        Red[tid] = (s0+s1)+(s2+s3);
    }
    __syncthreads();
    if (tid < 128){
        int b = b0 + tid;
        float v = Red[tid] + Red[tid+128];
        out[(size_t)b*OD + o] = v + g_c0[b]*g_G[o] + g_Bc[o] + bias[o];
    }
}

// ---------------- launch ----------------
extern "C" void kernel_launch(void* const* d_in, const int* in_sizes, int n_in,
                              void* d_out, int out_size){
    const float* X       = (const float*)d_in[0];
    const float* centers = (const float*)d_in[1];
    const float* sigmas  = (const float*)d_in[2];
    const float* gamma   = (const float*)d_in[3];
    const float* beta    = (const float*)d_in[4];
    const float* W       = (const float*)d_in[5];
    const float* bias    = (const float*)d_in[6];
    float* out = (float*)d_out;
    (void)in_sizes; (void)n_in; (void)out_size;

    cudaFuncSetAttribute(k1_frs,  cudaFuncAttributeMaxDynamicSharedMemorySize, 42112);
    cudaFuncSetAttribute(k2_wmma, cudaFuncAttributeMaxDynamicSharedMemorySize, K2_SMEM);

    k0a_prep <<<1152, 256>>>(centers, sigmas, X);               // 1
    k0_bsplit<<<dim3(8, 64), 256>>>(W, gamma, beta);            // 2
    k1_frs   <<<NB/8, 128, 42112>>>(X);                         // 3
    k2_wmma  <<<dim3(NB/128, OD), 256, K2_SMEM>>>(bias, out);   // 4 (profiled)
}

// round 12
// speedup vs baseline: 1.6151x; 1.4052x over previous
#include <cuda_runtime.h>
#include <cuda_fp16.h>
#include <mma.h>

using namespace nvcuda;

#define IN_D 256
#define RU   128
#define OD   64
#define NB   2048
#define DDIM 32896
#define HCONST 0.5f
#define EPS_C  1e-8f
#define LN_EPS_C 1e-5f

typedef unsigned long long ull;

// ---------------- device scratch (allocation-free) ----------------
__device__ float    g_S  [IN_D*RU];
__device__ float    g_CS [IN_D*RU];
__device__ float    g_K2 [RU];
__device__ float    g_G  [OD];
__device__ float    g_Bc [OD];
__device__ float    g_fsT[RU*NB];      // (frs*rstd) transposed: [r][b]
__device__ float    g_c0 [NB];         // -mu*rstd
__device__ float    g_Wt [OD*RU];      // tail weights gamma*W[o][32768+r]
__device__ unsigned g_Bh [256*4096];   // B fp16 [i=256][n_w=4096] f16x2, n_w = o*64 + r/2
__device__ unsigned g_Xhi[NB*128];     // X fp16 hi split [b][128 words]
__device__ unsigned g_Xlo[NB*128];     // X fp16 residual split

// ---------------- helpers ----------------
__device__ __forceinline__ ull pk2(float x){
    unsigned u = __float_as_uint(x);
    ull r; asm("mov.b64 %0, {%1, %1};" : "=l"(r) : "r"(u)); return r;
}
__device__ __forceinline__ void fma2(ull &d, ull a, ull b){
    asm("fma.rn.f32x2 %0, %1, %2, %0;" : "+l"(d) : "l"(a), "l"(b));
}
__device__ __forceinline__ void unpk(ull v, float &lo, float &hi){
    unsigned ulo, uhi;
    asm("mov.b64 {%0, %1}, %2;" : "=r"(ulo), "=r"(uhi) : "l"(v));
    lo = __uint_as_float(ulo); hi = __uint_as_float(uhi);
}
// fp16 2-term split of (a,b): hi = {h16(b),h16(a)}, lo = fp16 residuals
__device__ __forceinline__ void split_pack_h(float a, float b, unsigned &hi, unsigned &lo){
    unsigned h; asm("cvt.rn.f16x2.f32 %0, %1, %2;" : "=r"(h) : "f"(b), "f"(a));
    float ra, rb;
    asm("{.reg .f16 x, y;\n\t mov.b32 {x, y}, %2;\n\t cvt.f32.f16 %0, x;\n\t cvt.f32.f16 %1, y;}"
        : "=f"(ra), "=f"(rb) : "r"(h));
    float la = a - ra, lb = b - rb;
    unsigned l; asm("cvt.rn.f16x2.f32 %0, %1, %2;" : "=r"(l) : "f"(lb), "f"(la));
    hi = h; lo = l;
}
__device__ __forceinline__ unsigned pack_h2(float a, float b){
    unsigned h; asm("cvt.rn.f16x2.f32 %0, %1, %2;" : "=r"(h) : "f"(b), "f"(a));
    return h;
}
__device__ __forceinline__ unsigned smem_u32(const void* p){
    unsigned a;
    asm("{ .reg .u64 t; cvta.to.shared.u64 t, %1; cvt.u32.u64 %0, t; }" : "=r"(a) : "l"(p));
    return a;
}
__device__ __forceinline__ void cpa16(unsigned dst, const void* src){
    asm volatile("cp.async.cg.shared.global [%0], [%1], 16;" :: "r"(dst), "l"(src) : "memory");
}
#define CPA_COMMIT() asm volatile("cp.async.commit_group;" ::: "memory")
#define CPA_WAIT2()  asm volatile("cp.async.wait_group 2;" ::: "memory")
#define CPA_WAIT1()  asm volatile("cp.async.wait_group 1;" ::: "memory")
#define CPA_WAIT0()  asm volatile("cp.async.wait_group 0;" ::: "memory")

// ---------------- launch 1: k0a — X fp16 split + rule constants + K2 + zero G/Bc ----------------
__global__ void k0a_prep(const float* __restrict__ centers, const float* __restrict__ sigmas,
                         const float* __restrict__ X){
    __shared__ float red[256];
    int t = threadIdx.x, blk = blockIdx.x;
    if (blk < 1024){
        int p = blk*256 + t;
        float2 x = *(const float2*)(X + 2*(size_t)p);
        unsigned hi, lo; split_pack_h(x.x, x.y, hi, lo);
        g_Xhi[p] = hi; g_Xlo[p] = lo;
        if (blk < 128){
            int i = blk*256 + t;
            float sg = sigmas[i];
            float s  = HCONST/(sg*sg) + EPS_C;
            g_S[i]  = s;
            g_CS[i] = centers[i]*s;
        }
        if (blk == 0){
            if (t < OD)          g_G [t]      = 0.f;
            else if (t < 2*OD)   g_Bc[t - OD] = 0.f;
        }
    } else {
        int r = blk - 1024;
        float c = centers[t*RU + r], sg = sigmas[t*RU + r];
        float s = HCONST/(sg*sg) + EPS_C;
        red[t] = c*c*s;
        __syncthreads();
        for (int s2 = 128; s2 > 0; s2 >>= 1){
            if (t < s2) red[t] += red[t+s2];
            __syncthreads();
        }
        if (t == 0) g_K2[r] = red[0];
    }
}

// ---------------- launch 2: k0_bsplit — coalesced fp16 B build (+ tail fused at ic==7) ----------------
__global__ void k0_bsplit(const float* __restrict__ W, const float* __restrict__ gamma,
                          const float* __restrict__ beta){
    __shared__ float gw[128*33];
    __shared__ float rg[8], rb[8], trg[4], trb[4];
    const int ic = blockIdx.x, o = blockIdx.y;
    const int t = threadIdx.x, lane = t & 31, w = t >> 5;
    const int i0 = ic*32;
    float sg = 0.f, sb = 0.f;
    #pragma unroll
    for (int u = 0; u < 16; ++u){
        int e = t + u*256;
        int r = e >> 5, il = e & 31;
        int d = r*256 + i0 + il;
        float wv = W[(size_t)o*DDIM + d];
        float gv = gamma[d]*wv;
        gw[r*33 + il] = gv;
        sg += gv; sb += beta[d]*wv;
    }
    __syncthreads();
    #pragma unroll
    for (int u = 0; u < 8; ++u){
        int q = t + u*256;
        int il = q >> 6, rp = q & 63;
        float a = gw[(2*rp  )*33 + il];
        float b = gw[(2*rp+1)*33 + il];
        g_Bh[(size_t)(i0+il)*4096 + o*64 + rp] = pack_h2(a, b);
    }
    #pragma unroll
    for (int off = 16; off; off >>= 1){
        sg += __shfl_down_sync(0xffffffffu, sg, off);
        sb += __shfl_down_sync(0xffffffffu, sb, off);
    }
    if (lane == 0){ rg[w] = sg; rb[w] = sb; }
    __syncthreads();
    if (t == 0){
        float a = 0.f, b2 = 0.f;
        #pragma unroll
        for (int u = 0; u < 8; ++u){ a += rg[u]; b2 += rb[u]; }
        atomicAdd(&g_G[o], a); atomicAdd(&g_Bc[o], b2);
    }
    if (ic == 7){
        float tgv = 0.f, tbv = 0.f;
        if (t < 128){
            int d = 32768 + t;
            float wv = W[(size_t)o*DDIM + d];
            tgv = gamma[d]*wv;
            tbv = beta[d]*wv;
            g_Wt[o*RU + t] = tgv;
        }
        #pragma unroll
        for (int off = 16; off; off >>= 1){
            tgv += __shfl_down_sync(0xffffffffu, tgv, off);
            tbv += __shfl_down_sync(0xffffffffu, tbv, off);
        }
        if (lane == 0 && t < 128){ trg[w] = tgv; trb[w] = tbv; }
        __syncthreads();
        if (t == 0){
            atomicAdd(&g_G [o], trg[0]+trg[1]+trg[2]+trg[3]);
            atomicAdd(&g_Bc[o], trb[0]+trb[1]+trb[2]+trb[3]);
        }
    }
}

// ---------------- launch 3: k1 — firing levels + softmax + closed-form LN stats ----------------
__global__ __launch_bounds__(128,4) void k1_frs(const float* __restrict__ X){
    extern __shared__ float sm1[];
    float* Xs = sm1;             // [256][9]
    float* Ss = sm1 + 256*9;     // [32][128]
    float* Cs = Ss  + 32*128;    // [32][128]
    __shared__ float K2s[RU];
    const int tid  = threadIdx.x;
    const int b0   = blockIdx.x * 8;
    const int lane = tid & 31, wg = tid >> 5;
    if (tid < RU) K2s[tid] = g_K2[tid];
    for (int q = tid; q < 8*64; q += 128){
        int bb = q >> 6, i4 = (q & 63)*4;
        float4 v = *(const float4*)(X + (size_t)(b0+bb)*IN_D + i4);
        Xs[(i4+0)*9+bb]=v.x; Xs[(i4+1)*9+bb]=v.y;
        Xs[(i4+2)*9+bb]=v.z; Xs[(i4+3)*9+bb]=v.w;
    }
    ull A1p[2][2], A2p[2][2];
    #pragma unroll
    for (int bi = 0; bi < 2; ++bi){
        A1p[bi][0]=0ull; A1p[bi][1]=0ull; A2p[bi][0]=0ull; A2p[bi][1]=0ull;
    }
    for (int c = 0; c < 8; ++c){
        __syncthreads();
        for (int q = tid; q < 32*32; q += 128){
            int row = q >> 5, col4 = (q & 31)*4;
            *(float4*)(Ss + row*RU + col4) = *(const float4*)(g_S  + (size_t)(c*32+row)*RU + col4);
            *(float4*)(Cs + row*RU + col4) = *(const float4*)(g_CS + (size_t)(c*32+row)*RU + col4);
        }
        __syncthreads();
        #pragma unroll 4
        for (int k = 0; k < 32; ++k){
            int i = c*32 + k;
            float x0 = Xs[i*9 + wg*2 + 0];
            float x1 = Xs[i*9 + wg*2 + 1];
            ull xx0 = pk2(x0*x0), xx1 = pk2(x1*x1);
            ull xp0 = pk2(x0),    xp1 = pk2(x1);
            #pragma unroll
            for (int jp = 0; jp < 2; ++jp){
                ull s2 = *(const ull*)(Ss + k*RU + 2*lane + 64*jp);
                ull c2 = *(const ull*)(Cs + k*RU + 2*lane + 64*jp);
                fma2(A1p[0][jp], xx0, s2); fma2(A1p[1][jp], xx1, s2);
                fma2(A2p[0][jp], xp0, c2); fma2(A2p[1][jp], xp1, c2);
            }
        }
    }
    #pragma unroll
    for (int bi = 0; bi < 2; ++bi){
        float sx = 0.f, sxx = 0.f;
        #pragma unroll
        for (int t = 0; t < 8; ++t){
            float x = Xs[(lane + 32*t)*9 + wg*2 + bi];
            sx += x; sxx += x*x;
        }
        #pragma unroll
        for (int off = 16; off; off >>= 1){
            sx  += __shfl_xor_sync(0xffffffffu, sx,  off);
            sxx += __shfl_xor_sync(0xffffffffu, sxx, off);
        }
        float lg[4], e[4];
        #pragma unroll
        for (int jp = 0; jp < 2; ++jp){
            float a1l,a1h,a2l,a2h;
            unpk(A1p[bi][jp], a1l, a1h);
            unpk(A2p[bi][jp], a2l, a2h);
            int r = 2*lane + 64*jp;
            lg[2*jp+0] = -(a1l - 2.f*a2l + K2s[r+0]) * (1.f/256.f);
            lg[2*jp+1] = -(a1h - 2.f*a2h + K2s[r+1]) * (1.f/256.f);
        }
        float m = fmaxf(fmaxf(lg[0],lg[1]), fmaxf(lg[2],lg[3]));
        #pragma unroll
        for (int off = 16; off; off >>= 1)
            m = fmaxf(m, __shfl_xor_sync(0xffffffffu, m, off));
        float se = 0.f, se2 = 0.f;
        #pragma unroll
        for (int j = 0; j < 4; ++j){ e[j] = __expf(lg[j]-m); se += e[j]; se2 += e[j]*e[j]; }
        #pragma unroll
        for (int off = 16; off; off >>= 1){
            se  += __shfl_xor_sync(0xffffffffu, se,  off);
            se2 += __shfl_xor_sync(0xffffffffu, se2, off);
        }
        float inv  = 1.f/se;
        float mu   = (sx + 1.f) * (1.f/(float)DDIM);
        float ef2  = se2*inv*inv*(sxx + 1.f) * (1.f/(float)DDIM);
        float rstd = rsqrtf(ef2 - mu*mu + LN_EPS_C);
        int b = b0 + wg*2 + bi;
        float fr = inv*rstd;
        #pragma unroll
        for (int jp = 0; jp < 2; ++jp){
            int r = 2*lane + 64*jp;
            g_fsT[(size_t)(r  )*NB + b] = e[2*jp+0]*fr;
            g_fsT[(size_t)(r+1)*NB + b] = e[2*jp+1]*fr;
        }
        if (lane == 0) g_c0[b] = -mu*rstd;
    }
}

// ---------------- launch 4: k2 — fp16 wmma GEMM (2-pass A-split), 3-stage cp.async ----------------
// M=128 x N=128, K-chunks of 32 (8 chunks), 256 thr, 2 CTAs/SM.
// Row pitches 16B multiples: A 80B, B 272B.
#define A_LDE 40          // A row pitch in fp16 elements (80B)
#define B_LDE 136         // B row pitch in fp16 elements (272B)
#define R_AH 0u
#define R_AL 10240u
#define R_B  20480u
#define BUF_SZ 29184u
#define N_STG 3
#define OFF_RED 87552u    // 256 floats
#define OFF_WT  88576u    // 128 floats
#define K2_SMEM 89088u

__global__ __launch_bounds__(256,2) void k2_wmma(const float* __restrict__ bias,
                                                 float* __restrict__ out){
    extern __shared__ __align__(16) char sm[];
    float* Wts = (float*)(sm + OFF_WT);
    float* Ps  = (float*)sm;                 // epilogue overlay [bl + n*132]
    float* Red = (float*)(sm + OFF_RED);
    const unsigned base = smem_u32(sm);
    const int tid = threadIdx.x;
    const int b0  = blockIdx.x * 128;
    const int o   = blockIdx.y;
    const int w   = tid >> 5;
    const int mw  = w >> 1, nw = w & 1;      // 4x2 warps: 32m x 64n tiles

    if (tid < 128) Wts[tid] = g_Wt[o*RU + tid];

    auto issue = [&](int kc, unsigned bufb){
        #pragma unroll
        for (int u = 0; u < 2; ++u){
            int q = tid + u*256;             // 512: A 128 rows x 4 segs
            int row = q >> 2, s = q & 3;
            const unsigned* sh = g_Xhi + (size_t)(b0+row)*128 + kc*16 + s*4;
            const unsigned* sl = g_Xlo + (size_t)(b0+row)*128 + kc*16 + s*4;
            cpa16(bufb + R_AH + row*80 + s*16, sh);
            cpa16(bufb + R_AL + row*80 + s*16, sl);
        }
        {
            int q = tid + 0;                 // first 256 of 512 B items
            int k = q >> 4, s = q & 15;
            cpa16(bufb + R_B + k*272 + s*16, g_Bh + (size_t)(kc*32+k)*4096 + o*64 + s*4);
            q = tid + 256;
            k = q >> 4; s = q & 15;
            cpa16(bufb + R_B + k*272 + s*16, g_Bh + (size_t)(kc*32+k)*4096 + o*64 + s*4);
        }
    };

    wmma::fragment<wmma::accumulator,16,16,16,float> acc[2][4];
    #pragma unroll
    for (int mt = 0; mt < 2; ++mt)
        #pragma unroll
        for (int nt = 0; nt < 4; ++nt) wmma::fill_fragment(acc[mt][nt], 0.f);

    issue(0, base); CPA_COMMIT();
    issue(1, base + BUF_SZ); CPA_COMMIT();
    for (int kc = 0; kc < 8; ++kc){
        if (kc + 2 < 8){ issue(kc+2, base + ((kc+2)%N_STG)*BUF_SZ); CPA_COMMIT(); CPA_WAIT2(); }
        else if (kc + 1 < 8) CPA_WAIT1();
        else CPA_WAIT0();
        __syncthreads();
        const char* bufc = sm + (kc%N_STG)*BUF_SZ;
        const __half* Ah = (const __half*)(bufc + R_AH);
        const __half* Al = (const __half*)(bufc + R_AL);
        const __half* Bp = (const __half*)(bufc + R_B);
        #pragma unroll
        for (int ks = 0; ks < 2; ++ks){
            wmma::fragment<wmma::matrix_a,16,16,16,__half,wmma::row_major> ah[2], al[2];
            #pragma unroll
            for (int mt = 0; mt < 2; ++mt){
                wmma::load_matrix_sync(ah[mt], Ah + (mw*32 + mt*16)*A_LDE + ks*16, A_LDE);
                wmma::load_matrix_sync(al[mt], Al + (mw*32 + mt*16)*A_LDE + ks*16, A_LDE);
            }
            #pragma unroll
            for (int nt = 0; nt < 4; ++nt){
                wmma::fragment<wmma::matrix_b,16,16,16,__half,wmma::row_major> bf;
                wmma::load_matrix_sync(bf, Bp + ks*16*B_LDE + nw*64 + nt*16, B_LDE);
                #pragma unroll
                for (int mt = 0; mt < 2; ++mt){
                    wmma::mma_sync(acc[mt][nt], ah[mt], bf, acc[mt][nt]);
                    wmma::mma_sync(acc[mt][nt], al[mt], bf, acc[mt][nt]);
                }
            }
        }
        __syncthreads();
    }
    // stage P col-major: element (b_local, n) at Ps[bl + n*132]
    #pragma unroll
    for (int mt = 0; mt < 2; ++mt)
        #pragma unroll
        for (int nt = 0; nt < 4; ++nt)
            wmma::store_matrix_sync(Ps + (mw*32 + mt*16) + (size_t)(nw*64 + nt*16)*132,
                                    acc[mt][nt], 132, wmma::mem_col_major);
    __syncthreads();
    {   // rule reduction: 2 halves x 128 b, 64 rules each
        int half = tid >> 7, bl = tid & 127;
        int b = b0 + bl;
        float s0 = 0.f, s1 = 0.f, s2 = 0.f, s3 = 0.f;
        int rb0 = half*64;
        #pragma unroll
        for (int u = 0; u < 16; ++u){
            int r = rb0 + 4*u;
            s0 += g_fsT[(size_t)(r  )*NB + b] * (Ps[bl + (r  )*132] + Wts[r  ]);
            s1 += g_fsT[(size_t)(r+1)*NB + b] * (Ps[bl + (r+1)*132] + Wts[r+1]);
            s2 += g_fsT[(size_t)(r+2)*NB + b] * (Ps[bl + (r+2)*132] + Wts[r+2]);
            s3 += g_fsT[(size_t)(r+3)*NB + b] * (Ps[bl + (r+3)*132] + Wts[r+3]);
        }
        Red[tid] = (s0+s1)+(s2+s3);
    }
    __syncthreads();
    if (tid < 128){
        int b = b0 + tid;
        float v = Red[tid] + Red[tid+128];
        out[(size_t)b*OD + o] = v + g_c0[b]*g_G[o] + g_Bc[o] + bias[o];
    }
}

// ---------------- launch ----------------
extern "C" void kernel_launch(void* const* d_in, const int* in_sizes, int n_in,
                              void* d_out, int out_size){
    const float* X       = (const float*)d_in[0];
    const float* centers = (const float*)d_in[1];
    const float* sigmas  = (const float*)d_in[2];
    const float* gamma   = (const float*)d_in[3];
    const float* beta    = (const float*)d_in[4];
    const float* W       = (const float*)d_in[5];
    const float* bias    = (const float*)d_in[6];
    float* out = (float*)d_out;
    (void)in_sizes; (void)n_in; (void)out_size;

    cudaFuncSetAttribute(k1_frs,  cudaFuncAttributeMaxDynamicSharedMemorySize, 42112);
    cudaFuncSetAttribute(k2_wmma, cudaFuncAttributeMaxDynamicSharedMemorySize, K2_SMEM);

    k0a_prep <<<1152, 256>>>(centers, sigmas, X);               // 1
    k0_bsplit<<<dim3(8, 64), 256>>>(W, gamma, beta);            // 2
    k1_frs   <<<NB/8, 128, 42112>>>(X);                         // 3
    k2_wmma  <<<dim3(NB/128, OD), 256, K2_SMEM>>>(bias, out);   // 4 (profiled)
}

// round 13
// speedup vs baseline: 2.0865x; 1.2918x over previous
#include <cuda_runtime.h>
#include <cuda_fp16.h>
#include <mma.h>

using namespace nvcuda;

#define IN_D 256
#define RU   128
#define OD   64
#define NB   2048
#define DDIM 32896
#define HCONST 0.5f
#define EPS_C  1e-8f
#define LN_EPS_C 1e-5f

typedef unsigned long long ull;

// ---------------- device scratch (allocation-free) ----------------
__device__ float    g_S  [IN_D*RU];
__device__ float    g_CS [IN_D*RU];
__device__ float    g_K2 [RU];
__device__ float    g_G  [OD];
__device__ float    g_Bc [OD];
__device__ float    g_fsT[RU*NB];      // (frs*rstd) transposed: [r][b]
__device__ float    g_c0 [NB];         // -mu*rstd
__device__ float    g_Wt [OD*RU];      // tail weights gamma*W[o][32768+r]
__device__ unsigned g_Bh [256*4096];   // B fp16 [i=256][n_w=4096] f16x2, n_w = o*64 + r/2
__device__ unsigned g_Xh [NB*128];     // X fp16 [b][128 words]

// ---------------- helpers ----------------
__device__ __forceinline__ ull pk2(float x){
    unsigned u = __float_as_uint(x);
    ull r; asm("mov.b64 %0, {%1, %1};" : "=l"(r) : "r"(u)); return r;
}
__device__ __forceinline__ void fma2(ull &d, ull a, ull b){
    asm("fma.rn.f32x2 %0, %1, %2, %0;" : "+l"(d) : "l"(a), "l"(b));
}
__device__ __forceinline__ void unpk(ull v, float &lo, float &hi){
    unsigned ulo, uhi;
    asm("mov.b64 {%0, %1}, %2;" : "=r"(ulo), "=r"(uhi) : "l"(v));
    lo = __uint_as_float(ulo); hi = __uint_as_float(uhi);
}
__device__ __forceinline__ unsigned pack_h2(float a, float b){
    unsigned h; asm("cvt.rn.f16x2.f32 %0, %1, %2;" : "=r"(h) : "f"(b), "f"(a));
    return h;
}
__device__ __forceinline__ unsigned smem_u32(const void* p){
    unsigned a;
    asm("{ .reg .u64 t; cvta.to.shared.u64 t, %1; cvt.u32.u64 %0, t; }" : "=r"(a) : "l"(p));
    return a;
}
__device__ __forceinline__ void cpa16(unsigned dst, const void* src){
    asm volatile("cp.async.cg.shared.global [%0], [%1], 16;" :: "r"(dst), "l"(src) : "memory");
}
#define CPA_COMMIT() asm volatile("cp.async.commit_group;" ::: "memory")
#define CPA_WAIT2()  asm volatile("cp.async.wait_group 2;" ::: "memory")
#define CPA_WAIT1()  asm volatile("cp.async.wait_group 1;" ::: "memory")
#define CPA_WAIT0()  asm volatile("cp.async.wait_group 0;" ::: "memory")

// ---------------- launch 1: k0a — X fp16 pack + rule constants + K2 + zero G/Bc ----------------
__global__ void k0a_prep(const float* __restrict__ centers, const float* __restrict__ sigmas,
                         const float* __restrict__ X){
    __shared__ float red[256];
    int t = threadIdx.x, blk = blockIdx.x;
    if (blk < 1024){
        int p = blk*256 + t;
        float2 x = *(const float2*)(X + 2*(size_t)p);
        g_Xh[p] = pack_h2(x.x, x.y);
        if (blk < 128){
            int i = blk*256 + t;
            float sg = sigmas[i];
            float s  = HCONST/(sg*sg) + EPS_C;
            g_S[i]  = s;
            g_CS[i] = centers[i]*s;
        }
        if (blk == 0){
            if (t < OD)          g_G [t]      = 0.f;
            else if (t < 2*OD)   g_Bc[t - OD] = 0.f;
        }
    } else {
        int r = blk - 1024;
        float c = centers[t*RU + r], sg = sigmas[t*RU + r];
        float s = HCONST/(sg*sg) + EPS_C;
        red[t] = c*c*s;
        __syncthreads();
        for (int s2 = 128; s2 > 0; s2 >>= 1){
            if (t < s2) red[t] += red[t+s2];
            __syncthreads();
        }
        if (t == 0) g_K2[r] = red[0];
    }
}

// ---------------- launch 2: k0_bsplit — coalesced fp16 B build (+ tail fused at ic==7) ----------------
__global__ void k0_bsplit(const float* __restrict__ W, const float* __restrict__ gamma,
                          const float* __restrict__ beta){
    __shared__ float gw[128*33];
    __shared__ float rg[8], rb[8], trg[4], trb[4];
    const int ic = blockIdx.x, o = blockIdx.y;
    const int t = threadIdx.x, lane = t & 31, w = t >> 5;
    const int i0 = ic*32;
    float sg = 0.f, sb = 0.f;
    #pragma unroll
    for (int u = 0; u < 16; ++u){
        int e = t + u*256;
        int r = e >> 5, il = e & 31;
        int d = r*256 + i0 + il;
        float wv = W[(size_t)o*DDIM + d];
        float gv = gamma[d]*wv;
        gw[r*33 + il] = gv;
        sg += gv; sb += beta[d]*wv;
    }
    __syncthreads();
    #pragma unroll
    for (int u = 0; u < 8; ++u){
        int q = t + u*256;
        int il = q >> 6, rp = q & 63;
        float a = gw[(2*rp  )*33 + il];
        float b = gw[(2*rp+1)*33 + il];
        g_Bh[(size_t)(i0+il)*4096 + o*64 + rp] = pack_h2(a, b);
    }
    #pragma unroll
    for (int off = 16; off; off >>= 1){
        sg += __shfl_down_sync(0xffffffffu, sg, off);
        sb += __shfl_down_sync(0xffffffffu, sb, off);
    }
    if (lane == 0){ rg[w] = sg; rb[w] = sb; }
    __syncthreads();
    if (t == 0){
        float a = 0.f, b2 = 0.f;
        #pragma unroll
        for (int u = 0; u < 8; ++u){ a += rg[u]; b2 += rb[u]; }
        atomicAdd(&g_G[o], a); atomicAdd(&g_Bc[o], b2);
    }
    if (ic == 7){
        float tgv = 0.f, tbv = 0.f;
        if (t < 128){
            int d = 32768 + t;
            float wv = W[(size_t)o*DDIM + d];
            tgv = gamma[d]*wv;
            tbv = beta[d]*wv;
            g_Wt[o*RU + t] = tgv;
        }
        #pragma unroll
        for (int off = 16; off; off >>= 1){
            tgv += __shfl_down_sync(0xffffffffu, tgv, off);
            tbv += __shfl_down_sync(0xffffffffu, tbv, off);
        }
        if (lane == 0 && t < 128){ trg[w] = tgv; trb[w] = tbv; }
        __syncthreads();
        if (t == 0){
            atomicAdd(&g_G [o], trg[0]+trg[1]+trg[2]+trg[3]);
            atomicAdd(&g_Bc[o], trb[0]+trb[1]+trb[2]+trb[3]);
        }
    }
}

// ---------------- launch 3: k1 — firing levels + softmax + closed-form LN stats ----------------
__global__ __launch_bounds__(128,4) void k1_frs(const float* __restrict__ X){
    extern __shared__ float sm1[];
    float* Xs = sm1;             // [256][9]
    float* Ss = sm1 + 256*9;     // [32][128]
    float* Cs = Ss  + 32*128;    // [32][128]
    __shared__ float K2s[RU];
    const int tid  = threadIdx.x;
    const int b0   = blockIdx.x * 8;
    const int lane = tid & 31, wg = tid >> 5;
    if (tid < RU) K2s[tid] = g_K2[tid];
    for (int q = tid; q < 8*64; q += 128){
        int bb = q >> 6, i4 = (q & 63)*4;
        float4 v = *(const float4*)(X + (size_t)(b0+bb)*IN_D + i4);
        Xs[(i4+0)*9+bb]=v.x; Xs[(i4+1)*9+bb]=v.y;
        Xs[(i4+2)*9+bb]=v.z; Xs[(i4+3)*9+bb]=v.w;
    }
    ull A1p[2][2], A2p[2][2];
    #pragma unroll
    for (int bi = 0; bi < 2; ++bi){
        A1p[bi][0]=0ull; A1p[bi][1]=0ull; A2p[bi][0]=0ull; A2p[bi][1]=0ull;
    }
    for (int c = 0; c < 8; ++c){
        __syncthreads();
        for (int q = tid; q < 32*32; q += 128){
            int row = q >> 5, col4 = (q & 31)*4;
            *(float4*)(Ss + row*RU + col4) = *(const float4*)(g_S  + (size_t)(c*32+row)*RU + col4);
            *(float4*)(Cs + row*RU + col4) = *(const float4*)(g_CS + (size_t)(c*32+row)*RU + col4);
        }
        __syncthreads();
        #pragma unroll 4
        for (int k = 0; k < 32; ++k){
            int i = c*32 + k;
            float x0 = Xs[i*9 + wg*2 + 0];
            float x1 = Xs[i*9 + wg*2 + 1];
            ull xx0 = pk2(x0*x0), xx1 = pk2(x1*x1);
            ull xp0 = pk2(x0),    xp1 = pk2(x1);
            #pragma unroll
            for (int jp = 0; jp < 2; ++jp){
                ull s2 = *(const ull*)(Ss + k*RU + 2*lane + 64*jp);
                ull c2 = *(const ull*)(Cs + k*RU + 2*lane + 64*jp);
                fma2(A1p[0][jp], xx0, s2); fma2(A1p[1][jp], xx1, s2);
                fma2(A2p[0][jp], xp0, c2); fma2(A2p[1][jp], xp1, c2);
            }
        }
    }
    #pragma unroll
    for (int bi = 0; bi < 2; ++bi){
        float sx = 0.f, sxx = 0.f;
        #pragma unroll
        for (int t = 0; t < 8; ++t){
            float x = Xs[(lane + 32*t)*9 + wg*2 + bi];
            sx += x; sxx += x*x;
        }
        #pragma unroll
        for (int off = 16; off; off >>= 1){
            sx  += __shfl_xor_sync(0xffffffffu, sx,  off);
            sxx += __shfl_xor_sync(0xffffffffu, sxx, off);
        }
        float lg[4], e[4];
        #pragma unroll
        for (int jp = 0; jp < 2; ++jp){
            float a1l,a1h,a2l,a2h;
            unpk(A1p[bi][jp], a1l, a1h);
            unpk(A2p[bi][jp], a2l, a2h);
            int r = 2*lane + 64*jp;
            lg[2*jp+0] = -(a1l - 2.f*a2l + K2s[r+0]) * (1.f/256.f);
            lg[2*jp+1] = -(a1h - 2.f*a2h + K2s[r+1]) * (1.f/256.f);
        }
        float m = fmaxf(fmaxf(lg[0],lg[1]), fmaxf(lg[2],lg[3]));
        #pragma unroll
        for (int off = 16; off; off >>= 1)
            m = fmaxf(m, __shfl_xor_sync(0xffffffffu, m, off));
        float se = 0.f, se2 = 0.f;
        #pragma unroll
        for (int j = 0; j < 4; ++j){ e[j] = __expf(lg[j]-m); se += e[j]; se2 += e[j]*e[j]; }
        #pragma unroll
        for (int off = 16; off; off >>= 1){
            se  += __shfl_xor_sync(0xffffffffu, se,  off);
            se2 += __shfl_xor_sync(0xffffffffu, se2, off);
        }
        float inv  = 1.f/se;
        float mu   = (sx + 1.f) * (1.f/(float)DDIM);
        float ef2  = se2*inv*inv*(sxx + 1.f) * (1.f/(float)DDIM);
        float rstd = rsqrtf(ef2 - mu*mu + LN_EPS_C);
        int b = b0 + wg*2 + bi;
        float fr = inv*rstd;
        #pragma unroll
        for (int jp = 0; jp < 2; ++jp){
            int r = 2*lane + 64*jp;
            g_fsT[(size_t)(r  )*NB + b] = e[2*jp+0]*fr;
            g_fsT[(size_t)(r+1)*NB + b] = e[2*jp+1]*fr;
        }
        if (lane == 0) g_c0[b] = -mu*rstd;
    }
}

// ---------------- launch 4: k2 — fp16 wmma GEMM (single pass), 3-stage cp.async ----------------
// M=128 x N=128, K-chunks of 32 (8 chunks), 256 thr, 2 CTAs/SM.
// Row pitches 16B multiples: A 80B, B 272B.
#define A_LDE 40          // A row pitch in fp16 elements (80B)
#define B_LDE 136         // B row pitch in fp16 elements (272B)
#define R_A  0u
#define R_B  10240u
#define BUF_SZ 18944u
#define N_STG 3
#define OFF_RED 67584u    // after Ps overlay (128*132*4 = 67584)
#define OFF_WT  68608u
#define K2_SMEM 69120u

__global__ __launch_bounds__(256,2) void k2_wmma(const float* __restrict__ bias,
                                                 float* __restrict__ out){
    extern __shared__ __align__(16) char sm[];
    float* Wts = (float*)(sm + OFF_WT);
    float* Ps  = (float*)sm;                 // epilogue overlay [bl + n*132]
    float* Red = (float*)(sm + OFF_RED);
    const unsigned base = smem_u32(sm);
    const int tid = threadIdx.x;
    const int b0  = blockIdx.x * 128;
    const int o   = blockIdx.y;
    const int w   = tid >> 5;
    const int mw  = w >> 1, nw = w & 1;      // 4x2 warps: 32m x 64n tiles

    if (tid < 128) Wts[tid] = g_Wt[o*RU + tid];

    auto issue = [&](int kc, unsigned bufb){
        {
            int q = tid;                     // 512: A 128 rows x 4 segs
            int row = q >> 2, s = q & 3;
            cpa16(bufb + R_A + row*80 + s*16, g_Xh + (size_t)(b0+row)*128 + kc*16 + s*4);
            q = tid + 256;
            row = q >> 2; s = q & 3;
            cpa16(bufb + R_A + row*80 + s*16, g_Xh + (size_t)(b0+row)*128 + kc*16 + s*4);
        }
        {
            int q = tid;                     // 512: B 32 rows x 16 segs
            int k = q >> 4, s = q & 15;
            cpa16(bufb + R_B + k*272 + s*16, g_Bh + (size_t)(kc*32+k)*4096 + o*64 + s*4);
            q = tid + 256;
            k = q >> 4; s = q & 15;
            cpa16(bufb + R_B + k*272 + s*16, g_Bh + (size_t)(kc*32+k)*4096 + o*64 + s*4);
        }
    };

    wmma::fragment<wmma::accumulator,16,16,16,float> acc[2][4];
    #pragma unroll
    for (int mt = 0; mt < 2; ++mt)
        #pragma unroll
        for (int nt = 0; nt < 4; ++nt) wmma::fill_fragment(acc[mt][nt], 0.f);

    issue(0, base); CPA_COMMIT();
    issue(1, base + BUF_SZ); CPA_COMMIT();
    for (int kc = 0; kc < 8; ++kc){
        if (kc + 2 < 8){ issue(kc+2, base + ((kc+2)%N_STG)*BUF_SZ); CPA_COMMIT(); CPA_WAIT2(); }
        else if (kc + 1 < 8) CPA_WAIT1();
        else CPA_WAIT0();
        __syncthreads();
        const char* bufc = sm + (kc%N_STG)*BUF_SZ;
        const __half* Ap = (const __half*)(bufc + R_A);
        const __half* Bp = (const __half*)(bufc + R_B);
        #pragma unroll
        for (int ks = 0; ks < 2; ++ks){
            wmma::fragment<wmma::matrix_a,16,16,16,__half,wmma::row_major> af[2];
            #pragma unroll
            for (int mt = 0; mt < 2; ++mt)
                wmma::load_matrix_sync(af[mt], Ap + (mw*32 + mt*16)*A_LDE + ks*16, A_LDE);
            #pragma unroll
            for (int nt = 0; nt < 4; ++nt){
                wmma::fragment<wmma::matrix_b,16,16,16,__half,wmma::row_major> bf;
                wmma::load_matrix_sync(bf, Bp + ks*16*B_LDE + nw*64 + nt*16, B_LDE);
                #pragma unroll
                for (int mt = 0; mt < 2; ++mt)
                    wmma::mma_sync(acc[mt][nt], af[mt], bf, acc[mt][nt]);
            }
        }
        __syncthreads();
    }
    // stage P col-major: element (b_local, n) at Ps[bl + n*132]
    #pragma unroll
    for (int mt = 0; mt < 2; ++mt)
        #pragma unroll
        for (int nt = 0; nt < 4; ++nt)
            wmma::store_matrix_sync(Ps + (mw*32 + mt*16) + (size_t)(nw*64 + nt*16)*132,
                                    acc[mt][nt], 132, wmma::mem_col_major);
    __syncthreads();
    {   // rule reduction: 2 halves x 128 b, 64 rules each
        int half = tid >> 7, bl = tid & 127;
        int b = b0 + bl;
        float s0 = 0.f, s1 = 0.f, s2 = 0.f, s3 = 0.f;
        int rb0 = half*64;
        #pragma unroll
        for (int u = 0; u < 16; ++u){
            int r = rb0 + 4*u;
            s0 += g_fsT[(size_t)(r  )*NB + b] * (Ps[bl + (r  )*132] + Wts[r  ]);
            s1 += g_fsT[(size_t)(r+1)*NB + b] * (Ps[bl + (r+1)*132] + Wts[r+1]);
            s2 += g_fsT[(size_t)(r+2)*NB + b] * (Ps[bl + (r+2)*132] + Wts[r+2]);
            s3 += g_fsT[(size_t)(r+3)*NB + b] * (Ps[bl + (r+3)*132] + Wts[r+3]);
        }
        Red[tid] = (s0+s1)+(s2+s3);
    }
    __syncthreads();
    if (tid < 128){
        int b = b0 + tid;
        float v = Red[tid] + Red[tid+128];
        out[(size_t)b*OD + o] = v + g_c0[b]*g_G[o] + g_Bc[o] + bias[o];
    }
}

// ---------------- launch ----------------
extern "C" void kernel_launch(void* const* d_in, const int* in_sizes, int n_in,
                              void* d_out, int out_size){
    const float* X       = (const float*)d_in[0];
    const float* centers = (const float*)d_in[1];
    const float* sigmas  = (const float*)d_in[2];
    const float* gamma   = (const float*)d_in[3];
    const float* beta    = (const float*)d_in[4];
    const float* W       = (const float*)d_in[5];
    const float* bias    = (const float*)d_in[6];
    float* out = (float*)d_out;
    (void)in_sizes; (void)n_in; (void)out_size;

    cudaFuncSetAttribute(k1_frs,  cudaFuncAttributeMaxDynamicSharedMemorySize, 42112);
    cudaFuncSetAttribute(k2_wmma, cudaFuncAttributeMaxDynamicSharedMemorySize, K2_SMEM);

    k0a_prep <<<1152, 256>>>(centers, sigmas, X);               // 1
    k0_bsplit<<<dim3(8, 64), 256>>>(W, gamma, beta);            // 2
    k1_frs   <<<NB/8, 128, 42112>>>(X);                         // 3
    k2_wmma  <<<dim3(NB/128, OD), 256, K2_SMEM>>>(bias, out);   // 4 (profiled)
}

// round 14
// speedup vs baseline: 2.2946x; 1.0997x over previous
#include <cuda_runtime.h>
#include <cuda_fp16.h>
#include <mma.h>

using namespace nvcuda;

#define IN_D 256
#define RU   128
#define OD   64
#define NB   2048
#define DDIM 32896
#define HCONST 0.5f
#define EPS_C  1e-8f
#define LN_EPS_C 1e-5f

typedef unsigned long long ull;

// ---------------- device scratch (allocation-free) ----------------
__device__ float    g_S  [IN_D*RU];
__device__ float    g_CS [IN_D*RU];
__device__ float    g_K2 [RU];
__device__ float    g_Gp [OD*9];       // G partials  [o][slot], race-free (no atomics)
__device__ float    g_Bp [OD*9];       // Bc partials [o][slot]
__device__ float    g_fsT[RU*NB];      // (frs*rstd) transposed: [r][b]
__device__ float    g_c0 [NB];         // -mu*rstd
__device__ float    g_Wt [OD*RU];      // tail weights gamma*W[o][32768+r]
__device__ unsigned g_Bh [256*4096];   // B fp16 [i=256][n_w=4096] f16x2, n_w = o*64 + r/2
__device__ unsigned g_Xh [NB*128];     // X fp16 [b][128 words]

// ---------------- helpers ----------------
__device__ __forceinline__ ull pk2(float x){
    unsigned u = __float_as_uint(x);
    ull r; asm("mov.b64 %0, {%1, %1};" : "=l"(r) : "r"(u)); return r;
}
__device__ __forceinline__ void fma2(ull &d, ull a, ull b){
    asm("fma.rn.f32x2 %0, %1, %2, %0;" : "+l"(d) : "l"(a), "l"(b));
}
__device__ __forceinline__ void unpk(ull v, float &lo, float &hi){
    unsigned ulo, uhi;
    asm("mov.b64 {%0, %1}, %2;" : "=r"(ulo), "=r"(uhi) : "l"(v));
    lo = __uint_as_float(ulo); hi = __uint_as_float(uhi);
}
__device__ __forceinline__ unsigned pack_h2(float a, float b){
    unsigned h; asm("cvt.rn.f16x2.f32 %0, %1, %2;" : "=r"(h) : "f"(b), "f"(a));
    return h;
}
__device__ __forceinline__ unsigned smem_u32(const void* p){
    unsigned a;
    asm("{ .reg .u64 t; cvta.to.shared.u64 t, %1; cvt.u32.u64 %0, t; }" : "=r"(a) : "l"(p));
    return a;
}
__device__ __forceinline__ void cpa16(unsigned dst, const void* src){
    asm volatile("cp.async.cg.shared.global [%0], [%1], 16;" :: "r"(dst), "l"(src) : "memory");
}
#define CPA_COMMIT() asm volatile("cp.async.commit_group;" ::: "memory")
#define CPA_WAIT2()  asm volatile("cp.async.wait_group 2;" ::: "memory")
#define CPA_WAIT1()  asm volatile("cp.async.wait_group 1;" ::: "memory")
#define CPA_WAIT0()  asm volatile("cp.async.wait_group 0;" ::: "memory")

// ---------------- launch 1: k0_fused — B build + tail + X pack + rule consts + K2 ----------------
// blocks [0,512): bsplit (ic = blk&7, o = blk>>3); [512,1536): X pack (+S/CS for first 128);
// [1536,1664): K2 reduction.
__global__ void k0_fused(const float* __restrict__ W, const float* __restrict__ gamma,
                         const float* __restrict__ beta,
                         const float* __restrict__ centers, const float* __restrict__ sigmas,
                         const float* __restrict__ X){
    __shared__ float gw[128*33];
    __shared__ float rg[8], rb[8], trg[4], trb[4];
    __shared__ float red[256];
    const int t = threadIdx.x, blk = blockIdx.x;
    if (blk < 512){
        const int ic = blk & 7, o = blk >> 3;
        const int lane = t & 31, w = t >> 5;
        const int i0 = ic*32;
        float sg = 0.f, sb = 0.f;
        #pragma unroll
        for (int u = 0; u < 16; ++u){
            int e = t + u*256;
            int r = e >> 5, il = e & 31;
            int d = r*256 + i0 + il;
            float wv = W[(size_t)o*DDIM + d];
            float gv = gamma[d]*wv;
            gw[r*33 + il] = gv;
            sg += gv; sb += beta[d]*wv;
        }
        __syncthreads();
        #pragma unroll
        for (int u = 0; u < 8; ++u){
            int q = t + u*256;
            int il = q >> 6, rp = q & 63;
            float a = gw[(2*rp  )*33 + il];
            float b = gw[(2*rp+1)*33 + il];
            g_Bh[(size_t)(i0+il)*4096 + o*64 + rp] = pack_h2(a, b);
        }
        #pragma unroll
        for (int off = 16; off; off >>= 1){
            sg += __shfl_down_sync(0xffffffffu, sg, off);
            sb += __shfl_down_sync(0xffffffffu, sb, off);
        }
        if (lane == 0){ rg[w] = sg; rb[w] = sb; }
        __syncthreads();
        if (t == 0){
            float a = 0.f, b2 = 0.f;
            #pragma unroll
            for (int u = 0; u < 8; ++u){ a += rg[u]; b2 += rb[u]; }
            g_Gp[o*9 + ic] = a; g_Bp[o*9 + ic] = b2;
        }
        if (ic == 7){   // tail slot 8
            float tgv = 0.f, tbv = 0.f;
            if (t < 128){
                int d = 32768 + t;
                float wv = W[(size_t)o*DDIM + d];
                tgv = gamma[d]*wv;
                tbv = beta[d]*wv;
                g_Wt[o*RU + t] = tgv;
            }
            #pragma unroll
            for (int off = 16; off; off >>= 1){
                tgv += __shfl_down_sync(0xffffffffu, tgv, off);
                tbv += __shfl_down_sync(0xffffffffu, tbv, off);
            }
            if (lane == 0 && t < 128){ trg[w] = tgv; trb[w] = tbv; }
            __syncthreads();
            if (t == 0){
                g_Gp[o*9 + 8] = trg[0]+trg[1]+trg[2]+trg[3];
                g_Bp[o*9 + 8] = trb[0]+trb[1]+trb[2]+trb[3];
            }
        }
    } else if (blk < 1536){
        int b2 = blk - 512;
        int p = b2*256 + t;
        float2 x = *(const float2*)(X + 2*(size_t)p);
        g_Xh[p] = pack_h2(x.x, x.y);
        if (b2 < 128){
            int i = b2*256 + t;
            float sg = sigmas[i];
            float s  = HCONST/(sg*sg) + EPS_C;
            g_S[i]  = s;
            g_CS[i] = centers[i]*s;
        }
    } else {
        int r = blk - 1536;
        float c = centers[t*RU + r], sg = sigmas[t*RU + r];
        float s = HCONST/(sg*sg) + EPS_C;
        red[t] = c*c*s;
        __syncthreads();
        for (int s2 = 128; s2 > 0; s2 >>= 1){
            if (t < s2) red[t] += red[t+s2];
            __syncthreads();
        }
        if (t == 0) g_K2[r] = red[0];
    }
}

// ---------------- launch 2: k1 — firing levels + softmax + LN stats (cp.async S/C tiles) ----------------
// 16-row subchunks, 2-stage cp.async. Dynamic smem: Xs 9216 + Sb 16384 + Cb 16384 = 41984.
#define K1_SMEM 41984
__global__ __launch_bounds__(128,4) void k1_frs(const float* __restrict__ X){
    extern __shared__ float sm1[];
    float* Xs = sm1;                 // [256][9]
    float* Sb = sm1 + 2304;          // 2 stages x [16][128]
    float* Cb = Sb  + 4096;          // 2 stages x [16][128]
    __shared__ float K2s[RU];
    const int tid  = threadIdx.x;
    const int b0   = blockIdx.x * 8;
    const int lane = tid & 31, wg = tid >> 5;
    const unsigned sb_b = smem_u32(Sb), cb_b = smem_u32(Cb);
    if (tid < RU) K2s[tid] = g_K2[tid];
    for (int q = tid; q < 8*64; q += 128){
        int bb = q >> 6, i4 = (q & 63)*4;
        float4 v = *(const float4*)(X + (size_t)(b0+bb)*IN_D + i4);
        Xs[(i4+0)*9+bb]=v.x; Xs[(i4+1)*9+bb]=v.y;
        Xs[(i4+2)*9+bb]=v.z; Xs[(i4+3)*9+bb]=v.w;
    }
    auto issue = [&](int sc, int st){
        #pragma unroll
        for (int u = 0; u < 4; ++u){
            int q = tid + u*128;
            int rr = q >> 5, sg = q & 31;
            cpa16(sb_b + st*8192 + rr*512 + sg*16, g_S  + (size_t)(sc*16+rr)*RU + sg*4);
            cpa16(cb_b + st*8192 + rr*512 + sg*16, g_CS + (size_t)(sc*16+rr)*RU + sg*4);
        }
    };
    ull A1p[2][2], A2p[2][2];
    #pragma unroll
    for (int bi = 0; bi < 2; ++bi){
        A1p[bi][0]=0ull; A1p[bi][1]=0ull; A2p[bi][0]=0ull; A2p[bi][1]=0ull;
    }
    issue(0, 0); CPA_COMMIT();
    for (int sc = 0; sc < 16; ++sc){
        CPA_WAIT0();
        __syncthreads();            // publishes subchunk sc (and Xs on sc==0); frees stage (sc+1)&1
        if (sc + 1 < 16){ issue(sc+1, (sc+1)&1); CPA_COMMIT(); }
        const float* Ss = Sb + (sc&1)*2048;
        const float* Cs = Cb + (sc&1)*2048;
        #pragma unroll 4
        for (int k = 0; k < 16; ++k){
            int i = sc*16 + k;
            float x0 = Xs[i*9 + wg*2 + 0];
            float x1 = Xs[i*9 + wg*2 + 1];
            ull xx0 = pk2(x0*x0), xx1 = pk2(x1*x1);
            ull xp0 = pk2(x0),    xp1 = pk2(x1);
            #pragma unroll
            for (int jp = 0; jp < 2; ++jp){
                ull s2 = *(const ull*)(Ss + k*RU + 2*lane + 64*jp);
                ull c2 = *(const ull*)(Cs + k*RU + 2*lane + 64*jp);
                fma2(A1p[0][jp], xx0, s2); fma2(A1p[1][jp], xx1, s2);
                fma2(A2p[0][jp], xp0, c2); fma2(A2p[1][jp], xp1, c2);
            }
        }
    }
    #pragma unroll
    for (int bi = 0; bi < 2; ++bi){
        float sx = 0.f, sxx = 0.f;
        #pragma unroll
        for (int t = 0; t < 8; ++t){
            float x = Xs[(lane + 32*t)*9 + wg*2 + bi];
            sx += x; sxx += x*x;
        }
        #pragma unroll
        for (int off = 16; off; off >>= 1){
            sx  += __shfl_xor_sync(0xffffffffu, sx,  off);
            sxx += __shfl_xor_sync(0xffffffffu, sxx, off);
        }
        float lg[4], e[4];
        #pragma unroll
        for (int jp = 0; jp < 2; ++jp){
            float a1l,a1h,a2l,a2h;
            unpk(A1p[bi][jp], a1l, a1h);
            unpk(A2p[bi][jp], a2l, a2h);
            int r = 2*lane + 64*jp;
            lg[2*jp+0] = -(a1l - 2.f*a2l + K2s[r+0]) * (1.f/256.f);
            lg[2*jp+1] = -(a1h - 2.f*a2h + K2s[r+1]) * (1.f/256.f);
        }
        float m = fmaxf(fmaxf(lg[0],lg[1]), fmaxf(lg[2],lg[3]));
        #pragma unroll
        for (int off = 16; off; off >>= 1)
            m = fmaxf(m, __shfl_xor_sync(0xffffffffu, m, off));
        float se = 0.f, se2 = 0.f;
        #pragma unroll
        for (int j = 0; j < 4; ++j){ e[j] = __expf(lg[j]-m); se += e[j]; se2 += e[j]*e[j]; }
        #pragma unroll
        for (int off = 16; off; off >>= 1){
            se  += __shfl_xor_sync(0xffffffffu, se,  off);
            se2 += __shfl_xor_sync(0xffffffffu, se2, off);
        }
        float inv  = 1.f/se;
        float mu   = (sx + 1.f) * (1.f/(float)DDIM);
        float ef2  = se2*inv*inv*(sxx + 1.f) * (1.f/(float)DDIM);
        float rstd = rsqrtf(ef2 - mu*mu + LN_EPS_C);
        int b = b0 + wg*2 + bi;
        float fr = inv*rstd;
        #pragma unroll
        for (int jp = 0; jp < 2; ++jp){
            int r = 2*lane + 64*jp;
            g_fsT[(size_t)(r  )*NB + b] = e[2*jp+0]*fr;
            g_fsT[(size_t)(r+1)*NB + b] = e[2*jp+1]*fr;
        }
        if (lane == 0) g_c0[b] = -mu*rstd;
    }
}

// ---------------- launch 3: k2 — fp16 wmma GEMM, 4-stage cp.async, 1 barrier/chunk ----------------
// M=128 x N=128, K-chunks of 32 (8 chunks), 256 thr, 2 CTAs/SM.
#define A_LDE 40          // A row pitch fp16 (80B)
#define B_LDE 136         // B row pitch fp16 (272B)
#define R_A  0u
#define R_B  10240u
#define BUF_SZ 18944u
#define OFF_RED 75776u    // 256 floats (after 4 buffers)
#define OFF_WT  76800u    // 128 floats
#define OFF_GB  77312u    // 2 floats: G[o], Bc[o]
#define K2_SMEM 77376u

__global__ __launch_bounds__(256,2) void k2_wmma(const float* __restrict__ bias,
                                                 float* __restrict__ out){
    extern __shared__ __align__(16) char sm[];
    float* Wts = (float*)(sm + OFF_WT);
    float* Ps  = (float*)sm;                 // epilogue overlay [bl + n*132]
    float* Red = (float*)(sm + OFF_RED);
    float* GBs = (float*)(sm + OFF_GB);
    const unsigned base = smem_u32(sm);
    const int tid = threadIdx.x;
    const int b0  = blockIdx.x * 128;
    const int o   = blockIdx.y;
    const int w   = tid >> 5;
    const int mw  = w >> 1, nw = w & 1;      // 4x2 warps: 32m x 64n tiles

    if (tid < 128) Wts[tid] = g_Wt[o*RU + tid];
    if (tid == 0){
        float g = 0.f, bc = 0.f;
        #pragma unroll
        for (int s = 0; s < 9; ++s){ g += g_Gp[o*9+s]; bc += g_Bp[o*9+s]; }
        GBs[0] = g; GBs[1] = bc;
    }

    auto issue = [&](int kc, unsigned bufb){
        {
            int q = tid;                     // 512: A 128 rows x 4 segs
            int row = q >> 2, s = q & 3;
            cpa16(bufb + R_A + row*80 + s*16, g_Xh + (size_t)(b0+row)*128 + kc*16 + s*4);
            q = tid + 256;
            row = q >> 2; s = q & 3;
            cpa16(bufb + R_A + row*80 + s*16, g_Xh + (size_t)(b0+row)*128 + kc*16 + s*4);
        }
        {
            int q = tid;                     // 512: B 32 rows x 16 segs
            int k = q >> 4, s = q & 15;
            cpa16(bufb + R_B + k*272 + s*16, g_Bh + (size_t)(kc*32+k)*4096 + o*64 + s*4);
            q = tid + 256;
            k = q >> 4; s = q & 15;
            cpa16(bufb + R_B + k*272 + s*16, g_Bh + (size_t)(kc*32+k)*4096 + o*64 + s*4);
        }
    };

    wmma::fragment<wmma::accumulator,16,16,16,float> acc[2][4];
    #pragma unroll
    for (int mt = 0; mt < 2; ++mt)
        #pragma unroll
        for (int nt = 0; nt < 4; ++nt) wmma::fill_fragment(acc[mt][nt], 0.f);

    issue(0, base); CPA_COMMIT();
    issue(1, base + BUF_SZ); CPA_COMMIT();
    issue(2, base + 2*BUF_SZ); CPA_COMMIT();
    for (int kc = 0; kc < 8; ++kc){
        // wait so chunk kc is resident (allow min(2, 7-kc) newer groups in flight)
        if (kc <= 5)      CPA_WAIT2();
        else if (kc == 6) CPA_WAIT1();
        else              CPA_WAIT0();
        __syncthreads();  // all threads' cp.asyncs for kc visible; all done computing kc-1
        if (kc + 3 < 8){ issue(kc+3, base + ((kc+3)&3)*BUF_SZ); CPA_COMMIT(); }
        // writer targets (kc+3)&3 == (kc-1)&3, whose readers finished before the barrier.
        const char* bufc = sm + (kc&3)*BUF_SZ;
        const __half* Ap = (const __half*)(bufc + R_A);
        const __half* Bp = (const __half*)(bufc + R_B);
        #pragma unroll
        for (int ks = 0; ks < 2; ++ks){
            wmma::fragment<wmma::matrix_a,16,16,16,__half,wmma::row_major> af[2];
            #pragma unroll
            for (int mt = 0; mt < 2; ++mt)
                wmma::load_matrix_sync(af[mt], Ap + (mw*32 + mt*16)*A_LDE + ks*16, A_LDE);
            #pragma unroll
            for (int nt = 0; nt < 4; ++nt){
                wmma::fragment<wmma::matrix_b,16,16,16,__half,wmma::row_major> bf;
                wmma::load_matrix_sync(bf, Bp + ks*16*B_LDE + nw*64 + nt*16, B_LDE);
                #pragma unroll
                for (int mt = 0; mt < 2; ++mt)
                    wmma::mma_sync(acc[mt][nt], af[mt], bf, acc[mt][nt]);
            }
        }
    }
    __syncthreads();   // mainloop fully done before Ps overlay overwrites buffers
    #pragma unroll
    for (int mt = 0; mt < 2; ++mt)
        #pragma unroll
        for (int nt = 0; nt < 4; ++nt)
            wmma::store_matrix_sync(Ps + (mw*32 + mt*16) + (size_t)(nw*64 + nt*16)*132,
                                    acc[mt][nt], 132, wmma::mem_col_major);
    __syncthreads();
    {   // rule reduction: 2 halves x 128 b, 64 rules each
        int half = tid >> 7, bl = tid & 127;
        int b = b0 + bl;
        float s0 = 0.f, s1 = 0.f, s2 = 0.f, s3 = 0.f;
        int rb0 = half*64;
        #pragma unroll
        for (int u = 0; u < 16; ++u){
            int r = rb0 + 4*u;
            s0 += g_fsT[(size_t)(r  )*NB + b] * (Ps[bl + (r  )*132] + Wts[r  ]);
            s1 += g_fsT[(size_t)(r+1)*NB + b] * (Ps[bl + (r+1)*132] + Wts[r+1]);
            s2 += g_fsT[(size_t)(r+2)*NB + b] * (Ps[bl + (r+2)*132] + Wts[r+2]);
            s3 += g_fsT[(size_t)(r+3)*NB + b] * (Ps[bl + (r+3)*132] + Wts[r+3]);
        }
        Red[tid] = (s0+s1)+(s2+s3);
    }
    __syncthreads();
    if (tid < 128){
        int b = b0 + tid;
        float v = Red[tid] + Red[tid+128];
        out[(size_t)b*OD + o] = v + g_c0[b]*GBs[0] + GBs[1] + bias[o];
    }
}

// ---------------- launch ----------------
extern "C" void kernel_launch(void* const* d_in, const int* in_sizes, int n_in,
                              void* d_out, int out_size){
    const float* X       = (const float*)d_in[0];
    const float* centers = (const float*)d_in[1];
    const float* sigmas  = (const float*)d_in[2];
    const float* gamma   = (const float*)d_in[3];
    const float* beta    = (const float*)d_in[4];
    const float* W       = (const float*)d_in[5];
    const float* bias    = (const float*)d_in[6];
    float* out = (float*)d_out;
    (void)in_sizes; (void)n_in; (void)out_size;

    cudaFuncSetAttribute(k1_frs,  cudaFuncAttributeMaxDynamicSharedMemorySize, K1_SMEM);
    cudaFuncSetAttribute(k2_wmma, cudaFuncAttributeMaxDynamicSharedMemorySize, K2_SMEM);

    k0_fused <<<1664, 256>>>(W, gamma, beta, centers, sigmas, X);   // 1
    k1_frs   <<<NB/8, 128, K1_SMEM>>>(X);                           // 2
    k2_wmma  <<<dim3(NB/128, OD), 256, K2_SMEM>>>(bias, out);       // 3
}

// round 15
// speedup vs baseline: 2.4749x; 1.0786x over previous
#include <cuda_runtime.h>
#include <cuda_fp16.h>

#define IN_D 256
#define RU   128
#define OD   64
#define NB   2048
#define DDIM 32896
#define HCONST 0.5f
#define EPS_C  1e-8f
#define LN_EPS_C 1e-5f

typedef unsigned long long ull;

// ---------------- device scratch (allocation-free) ----------------
__device__ float    g_S  [IN_D*RU];
__device__ float    g_CS [IN_D*RU];
__device__ float    g_K2 [RU];
__device__ float    g_Gp [OD*9];       // G partials  [o][slot], race-free
__device__ float    g_Bp [OD*9];       // Bc partials [o][slot]
__device__ float    g_fsT[RU*NB];      // (frs*rstd) transposed: [r][b]
__device__ float    g_c0 [NB];         // -mu*rstd
__device__ float    g_Wt [OD*RU];      // tail weights gamma*W[o][32768+r]
__device__ unsigned g_Bh [256*4096];   // B fp16 [i=256][n_w=4096] f16x2, n_w = o*64 + r/2
__device__ unsigned g_Xh [NB*128];     // X fp16 [b][128 words]

// ---------------- helpers ----------------
__device__ __forceinline__ ull pk2(float x){
    unsigned u = __float_as_uint(x);
    ull r; asm("mov.b64 %0, {%1, %1};" : "=l"(r) : "r"(u)); return r;
}
__device__ __forceinline__ void fma2(ull &d, ull a, ull b){
    asm("fma.rn.f32x2 %0, %1, %2, %0;" : "+l"(d) : "l"(a), "l"(b));
}
__device__ __forceinline__ void unpk(ull v, float &lo, float &hi){
    unsigned ulo, uhi;
    asm("mov.b64 {%0, %1}, %2;" : "=r"(ulo), "=r"(uhi) : "l"(v));
    lo = __uint_as_float(ulo); hi = __uint_as_float(uhi);
}
__device__ __forceinline__ unsigned pack_h2(float a, float b){
    unsigned h; asm("cvt.rn.f16x2.f32 %0, %1, %2;" : "=r"(h) : "f"(b), "f"(a));
    return h;
}
__device__ __forceinline__ unsigned smem_u32(const void* p){
    unsigned a;
    asm("{ .reg .u64 t; cvta.to.shared.u64 t, %1; cvt.u32.u64 %0, t; }" : "=r"(a) : "l"(p));
    return a;
}
__device__ __forceinline__ void cpa16(unsigned dst, const void* src){
    asm volatile("cp.async.cg.shared.global [%0], [%1], 16;" :: "r"(dst), "l"(src) : "memory");
}
#define CPA_COMMIT() asm volatile("cp.async.commit_group;" ::: "memory")
#define CPA_WAIT2()  asm volatile("cp.async.wait_group 2;" ::: "memory")
#define CPA_WAIT1()  asm volatile("cp.async.wait_group 1;" ::: "memory")
#define CPA_WAIT0()  asm volatile("cp.async.wait_group 0;" ::: "memory")

__device__ __forceinline__ void ldm4(unsigned* r, unsigned addr){
    asm volatile("ldmatrix.sync.aligned.m8n8.x4.shared.b16 {%0,%1,%2,%3}, [%4];"
        : "=r"(r[0]), "=r"(r[1]), "=r"(r[2]), "=r"(r[3]) : "r"(addr));
}
__device__ __forceinline__ void ldm4t(unsigned* r, unsigned addr){
    asm volatile("ldmatrix.sync.aligned.m8n8.x4.trans.shared.b16 {%0,%1,%2,%3}, [%4];"
        : "=r"(r[0]), "=r"(r[1]), "=r"(r[2]), "=r"(r[3]) : "r"(addr));
}
__device__ __forceinline__ void mma16816(float* d, const unsigned* a, const unsigned* b){
    asm volatile("mma.sync.aligned.m16n8k16.row.col.f32.f16.f16.f32 "
        "{%0,%1,%2,%3}, {%4,%5,%6,%7}, {%8,%9}, {%0,%1,%2,%3};"
        : "+f"(d[0]), "+f"(d[1]), "+f"(d[2]), "+f"(d[3])
        : "r"(a[0]), "r"(a[1]), "r"(a[2]), "r"(a[3]), "r"(b[0]), "r"(b[1]));
}

// ---------------- launch 1: k0_fused — B build + tail + X pack(MLP8) + rule consts + K2 ----------------
// blocks [0,512): bsplit; [512,640): X pack (8 pairs/thr) + S/CS; [640,768): K2.
__global__ void k0_fused(const float* __restrict__ W, const float* __restrict__ gamma,
                         const float* __restrict__ beta,
                         const float* __restrict__ centers, const float* __restrict__ sigmas,
                         const float* __restrict__ X){
    __shared__ float gw[128*33];
    __shared__ float rg[8], rb[8], trg[4], trb[4];
    __shared__ float red[256];
    const int t = threadIdx.x, blk = blockIdx.x;
    if (blk < 512){
        const int ic = blk & 7, o = blk >> 3;
        const int lane = t & 31, w = t >> 5;
        const int i0 = ic*32;
        float sg = 0.f, sb = 0.f;
        #pragma unroll
        for (int u = 0; u < 16; ++u){
            int e = t + u*256;
            int r = e >> 5, il = e & 31;
            int d = r*256 + i0 + il;
            float wv = W[(size_t)o*DDIM + d];
            float gv = gamma[d]*wv;
            gw[r*33 + il] = gv;
            sg += gv; sb += beta[d]*wv;
        }
        __syncthreads();
        #pragma unroll
        for (int u = 0; u < 8; ++u){
            int q = t + u*256;
            int il = q >> 6, rp = q & 63;
            float a = gw[(2*rp  )*33 + il];
            float b = gw[(2*rp+1)*33 + il];
            g_Bh[(size_t)(i0+il)*4096 + o*64 + rp] = pack_h2(a, b);
        }
        #pragma unroll
        for (int off = 16; off; off >>= 1){
            sg += __shfl_down_sync(0xffffffffu, sg, off);
            sb += __shfl_down_sync(0xffffffffu, sb, off);
        }
        if (lane == 0){ rg[w] = sg; rb[w] = sb; }
        __syncthreads();
        if (t == 0){
            float a = 0.f, b2 = 0.f;
            #pragma unroll
            for (int u = 0; u < 8; ++u){ a += rg[u]; b2 += rb[u]; }
            g_Gp[o*9 + ic] = a; g_Bp[o*9 + ic] = b2;
        }
        if (ic == 7){
            float tgv = 0.f, tbv = 0.f;
            if (t < 128){
                int d = 32768 + t;
                float wv = W[(size_t)o*DDIM + d];
                tgv = gamma[d]*wv;
                tbv = beta[d]*wv;
                g_Wt[o*RU + t] = tgv;
            }
            #pragma unroll
            for (int off = 16; off; off >>= 1){
                tgv += __shfl_down_sync(0xffffffffu, tgv, off);
                tbv += __shfl_down_sync(0xffffffffu, tbv, off);
            }
            if (lane == 0 && t < 128){ trg[w] = tgv; trb[w] = tbv; }
            __syncthreads();
            if (t == 0){
                g_Gp[o*9 + 8] = trg[0]+trg[1]+trg[2]+trg[3];
                g_Bp[o*9 + 8] = trb[0]+trb[1]+trb[2]+trb[3];
            }
        }
    } else if (blk < 640){
        int b2 = blk - 512;
        #pragma unroll
        for (int u = 0; u < 8; ++u){
            int p = b2*2048 + t + u*256;
            float2 x = *(const float2*)(X + 2*(size_t)p);
            g_Xh[p] = pack_h2(x.x, x.y);
        }
        int i = b2*256 + t;
        float sg = sigmas[i];
        float s  = HCONST/(sg*sg) + EPS_C;
        g_S[i]  = s;
        g_CS[i] = centers[i]*s;
    } else {
        int r = blk - 640;
        float c = centers[t*RU + r], sg = sigmas[t*RU + r];
        float s = HCONST/(sg*sg) + EPS_C;
        red[t] = c*c*s;
        __syncthreads();
        for (int s2 = 128; s2 > 0; s2 >>= 1){
            if (t < s2) red[t] += red[t+s2];
            __syncthreads();
        }
        if (t == 0) g_K2[r] = red[0];
    }
}

// ---------------- launch 2: k1 — firing levels + softmax + LN stats (cp.async S/C tiles) ----------------
#define K1_SMEM 41984
__global__ __launch_bounds__(128,4) void k1_frs(const float* __restrict__ X){
    extern __shared__ float sm1[];
    float* Xs = sm1;                 // [256][9]
    float* Sb = sm1 + 2304;          // 2 stages x [16][128]
    float* Cb = Sb  + 4096;
    __shared__ float K2s[RU];
    const int tid  = threadIdx.x;
    const int b0   = blockIdx.x * 8;
    const int lane = tid & 31, wg = tid >> 5;
    const unsigned sb_b = smem_u32(Sb), cb_b = smem_u32(Cb);
    if (tid < RU) K2s[tid] = g_K2[tid];
    for (int q = tid; q < 8*64; q += 128){
        int bb = q >> 6, i4 = (q & 63)*4;
        float4 v = *(const float4*)(X + (size_t)(b0+bb)*IN_D + i4);
        Xs[(i4+0)*9+bb]=v.x; Xs[(i4+1)*9+bb]=v.y;
        Xs[(i4+2)*9+bb]=v.z; Xs[(i4+3)*9+bb]=v.w;
    }
    auto issue = [&](int sc, int st){
        #pragma unroll
        for (int u = 0; u < 4; ++u){
            int q = tid + u*128;
            int rr = q >> 5, sg = q & 31;
            cpa16(sb_b + st*8192 + rr*512 + sg*16, g_S  + (size_t)(sc*16+rr)*RU + sg*4);
            cpa16(cb_b + st*8192 + rr*512 + sg*16, g_CS + (size_t)(sc*16+rr)*RU + sg*4);
        }
    };
    ull A1p[2][2], A2p[2][2];
    #pragma unroll
    for (int bi = 0; bi < 2; ++bi){
        A1p[bi][0]=0ull; A1p[bi][1]=0ull; A2p[bi][0]=0ull; A2p[bi][1]=0ull;
    }
    issue(0, 0); CPA_COMMIT();
    for (int sc = 0; sc < 16; ++sc){
        CPA_WAIT0();
        __syncthreads();
        if (sc + 1 < 16){ issue(sc+1, (sc+1)&1); CPA_COMMIT(); }
        const float* Ss = Sb + (sc&1)*2048;
        const float* Cs = Cb + (sc&1)*2048;
        #pragma unroll 4
        for (int k = 0; k < 16; ++k){
            int i = sc*16 + k;
            float x0 = Xs[i*9 + wg*2 + 0];
            float x1 = Xs[i*9 + wg*2 + 1];
            ull xx0 = pk2(x0*x0), xx1 = pk2(x1*x1);
            ull xp0 = pk2(x0),    xp1 = pk2(x1);
            #pragma unroll
            for (int jp = 0; jp < 2; ++jp){
                ull s2 = *(const ull*)(Ss + k*RU + 2*lane + 64*jp);
                ull c2 = *(const ull*)(Cs + k*RU + 2*lane + 64*jp);
                fma2(A1p[0][jp], xx0, s2); fma2(A1p[1][jp], xx1, s2);
                fma2(A2p[0][jp], xp0, c2); fma2(A2p[1][jp], xp1, c2);
            }
        }
    }
    #pragma unroll
    for (int bi = 0; bi < 2; ++bi){
        float sx = 0.f, sxx = 0.f;
        #pragma unroll
        for (int t = 0; t < 8; ++t){
            float x = Xs[(lane + 32*t)*9 + wg*2 + bi];
            sx += x; sxx += x*x;
        }
        #pragma unroll
        for (int off = 16; off; off >>= 1){
            sx  += __shfl_xor_sync(0xffffffffu, sx,  off);
            sxx += __shfl_xor_sync(0xffffffffu, sxx, off);
        }
        float lg[4], e[4];
        #pragma unroll
        for (int jp = 0; jp < 2; ++jp){
            float a1l,a1h,a2l,a2h;
            unpk(A1p[bi][jp], a1l, a1h);
            unpk(A2p[bi][jp], a2l, a2h);
            int r = 2*lane + 64*jp;
            lg[2*jp+0] = -(a1l - 2.f*a2l + K2s[r+0]) * (1.f/256.f);
            lg[2*jp+1] = -(a1h - 2.f*a2h + K2s[r+1]) * (1.f/256.f);
        }
        float m = fmaxf(fmaxf(lg[0],lg[1]), fmaxf(lg[2],lg[3]));
        #pragma unroll
        for (int off = 16; off; off >>= 1)
            m = fmaxf(m, __shfl_xor_sync(0xffffffffu, m, off));
        float se = 0.f, se2 = 0.f;
        #pragma unroll
        for (int j = 0; j < 4; ++j){ e[j] = __expf(lg[j]-m); se += e[j]; se2 += e[j]*e[j]; }
        #pragma unroll
        for (int off = 16; off; off >>= 1){
            se  += __shfl_xor_sync(0xffffffffu, se,  off);
            se2 += __shfl_xor_sync(0xffffffffu, se2, off);
        }
        float inv  = 1.f/se;
        float mu   = (sx + 1.f) * (1.f/(float)DDIM);
        float ef2  = se2*inv*inv*(sxx + 1.f) * (1.f/(float)DDIM);
        float rstd = rsqrtf(ef2 - mu*mu + LN_EPS_C);
        int b = b0 + wg*2 + bi;
        float fr = inv*rstd;
        #pragma unroll
        for (int jp = 0; jp < 2; ++jp){
            int r = 2*lane + 64*jp;
            g_fsT[(size_t)(r  )*NB + b] = e[2*jp+0]*fr;
            g_fsT[(size_t)(r+1)*NB + b] = e[2*jp+1]*fr;
        }
        if (lane == 0) g_c0[b] = -mu*rstd;
    }
}

// ---------------- launch 3: k2 — fp16 GEMM via ldmatrix/mma.sync, 4-stage cp.async ----------------
// M=128 x N=128, K-chunks of 32, 256 thr (8 warps, 4x2, warp tile 32m x 64n), 2 CTAs/SM.
#define A_PITCH 80        // A row pitch bytes
#define B_PITCH 272       // B row pitch bytes
#define R_A  0u
#define R_B  10240u
#define BUF_SZ 18944u
#define OFF_RED 75776u    // 256 floats (after 4 buffers; Ps overlay 67568B fits below)
#define OFF_WT  76800u    // 128 floats
#define OFF_GB  77312u    // 2 floats
#define K2_SMEM 77376u

__global__ __launch_bounds__(256,2) void k2_mma(const float* __restrict__ bias,
                                                float* __restrict__ out){
    extern __shared__ __align__(16) char sm[];
    float* Wts = (float*)(sm + OFF_WT);
    float* Ps  = (float*)sm;                 // epilogue overlay [bl + n*132]
    float* Red = (float*)(sm + OFF_RED);
    float* GBs = (float*)(sm + OFF_GB);
    const unsigned base = smem_u32(sm);
    const int tid = threadIdx.x;
    const int b0  = blockIdx.x * 128;
    const int o   = blockIdx.y;
    const int w   = tid >> 5, lane = tid & 31;
    const int mw  = w >> 1, nw = w & 1;      // 4x2 warps: 32m x 64n tiles

    if (tid < 128) Wts[tid] = g_Wt[o*RU + tid];
    if (tid == 0){
        float g = 0.f, bc = 0.f;
        #pragma unroll
        for (int s = 0; s < 9; ++s){ g += g_Gp[o*9+s]; bc += g_Bp[o*9+s]; }
        GBs[0] = g; GBs[1] = bc;
    }

    auto issue = [&](int kc, unsigned bufb){
        {
            int q = tid;                     // 512: A 128 rows x 4 segs
            int row = q >> 2, s = q & 3;
            cpa16(bufb + R_A + row*A_PITCH + s*16, g_Xh + (size_t)(b0+row)*128 + kc*16 + s*4);
            q = tid + 256;
            row = q >> 2; s = q & 3;
            cpa16(bufb + R_A + row*A_PITCH + s*16, g_Xh + (size_t)(b0+row)*128 + kc*16 + s*4);
        }
        {
            int q = tid;                     // 512: B 32 rows x 16 segs
            int k = q >> 4, s = q & 15;
            cpa16(bufb + R_B + k*B_PITCH + s*16, g_Bh + (size_t)(kc*32+k)*4096 + o*64 + s*4);
            q = tid + 256;
            k = q >> 4; s = q & 15;
            cpa16(bufb + R_B + k*B_PITCH + s*16, g_Bh + (size_t)(kc*32+k)*4096 + o*64 + s*4);
        }
    };

    // per-lane ldmatrix address offsets (within buffer)
    const unsigned arow = (unsigned)(mw*32) + (lane&7) + ((lane>>3)&1)*8;
    const unsigned aoff = arow*A_PITCH + ((lane>>4)*16);
    const unsigned krow = (lane&7) + ((lane>>3)&1)*8;
    const unsigned boff = krow*B_PITCH + (unsigned)nw*128 + ((lane>>4)*16);

    float acc[2][8][4];
    #pragma unroll
    for (int mt = 0; mt < 2; ++mt)
        #pragma unroll
        for (int nt = 0; nt < 8; ++nt)
            #pragma unroll
            for (int i = 0; i < 4; ++i) acc[mt][nt][i] = 0.f;

    issue(0, base); CPA_COMMIT();
    issue(1, base + BUF_SZ); CPA_COMMIT();
    issue(2, base + 2*BUF_SZ); CPA_COMMIT();
    for (int kc = 0; kc < 8; ++kc){
        if (kc <= 5)      CPA_WAIT2();
        else if (kc == 6) CPA_WAIT1();
        else              CPA_WAIT0();
        __syncthreads();
        if (kc + 3 < 8){ issue(kc+3, base + ((kc+3)&3)*BUF_SZ); CPA_COMMIT(); }
        const unsigned ab = base + (kc&3)*BUF_SZ + R_A + aoff;
        const unsigned bb = base + (kc&3)*BUF_SZ + R_B + boff;
        unsigned Af[2][2][4];      // [mt][ks]
        unsigned Bf[2][8][2];      // [ks][nt]
        ldm4(Af[0][0], ab);
        ldm4(Af[0][1], ab + 32);
        ldm4(Af[1][0], ab + 16*A_PITCH);
        ldm4(Af[1][1], ab + 16*A_PITCH + 32);
        #pragma unroll
        for (int ks = 0; ks < 2; ++ks)
            #pragma unroll
            for (int ntp = 0; ntp < 4; ++ntp)
                ldm4t(&Bf[ks][2*ntp][0], bb + ks*16*B_PITCH + ntp*32);
        #pragma unroll
        for (int ks = 0; ks < 2; ++ks)
            #pragma unroll
            for (int nt = 0; nt < 8; ++nt)
                #pragma unroll
                for (int mt = 0; mt < 2; ++mt)
                    mma16816(acc[mt][nt], Af[mt][ks], Bf[ks][nt]);
    }
    __syncthreads();   // mainloop fully done before Ps overlay overwrites buffers
    {   // stage P: d-frag element (r,c): r = lane>>2 (+8), c = (lane&3)*2 (+1)
        int r0 = mw*32 + (lane>>2);
        int c0 = nw*64 + (lane&3)*2;
        #pragma unroll
        for (int mt = 0; mt < 2; ++mt)
            #pragma unroll
            for (int nt = 0; nt < 8; ++nt){
                int r = r0 + mt*16, c = c0 + nt*8;
                Ps[r     + (c  )*132] = acc[mt][nt][0];
                Ps[r     + (c+1)*132] = acc[mt][nt][1];
                Ps[r + 8 + (c  )*132] = acc[mt][nt][2];
                Ps[r + 8 + (c+1)*132] = acc[mt][nt][3];
            }
    }
    __syncthreads();
    {   // rule reduction: 2 halves x 128 b, 64 rules each
        int half = tid >> 7, bl = tid & 127;
        int b = b0 + bl;
        float s0 = 0.f, s1 = 0.f, s2 = 0.f, s3 = 0.f;
        int rb0 = half*64;
        #pragma unroll
        for (int u = 0; u < 16; ++u){
            int r = rb0 + 4*u;
            s0 += g_fsT[(size_t)(r  )*NB + b] * (Ps[bl + (r  )*132] + Wts[r  ]);
            s1 += g_fsT[(size_t)(r+1)*NB + b] * (Ps[bl + (r+1)*132] + Wts[r+1]);
            s2 += g_fsT[(size_t)(r+2)*NB + b] * (Ps[bl + (r+2)*132] + Wts[r+2]);
            s3 += g_fsT[(size_t)(r+3)*NB + b] * (Ps[bl + (r+3)*132] + Wts[r+3]);
        }
        Red[tid] = (s0+s1)+(s2+s3);
    }
    __syncthreads();
    if (tid < 128){
        int b = b0 + tid;
        float v = Red[tid] + Red[tid+128];
        out[(size_t)b*OD + o] = v + g_c0[b]*GBs[0] + GBs[1] + bias[o];
    }
}

// ---------------- launch ----------------
extern "C" void kernel_launch(void* const* d_in, const int* in_sizes, int n_in,
                              void* d_out, int out_size){
    const float* X       = (const float*)d_in[0];
    const float* centers = (const float*)d_in[1];
    const float* sigmas  = (const float*)d_in[2];
    const float* gamma   = (const float*)d_in[3];
    const float* beta    = (const float*)d_in[4];
    const float* W       = (const float*)d_in[5];
    const float* bias    = (const float*)d_in[6];
    float* out = (float*)d_out;
    (void)in_sizes; (void)n_in; (void)out_size;

    cudaFuncSetAttribute(k1_frs, cudaFuncAttributeMaxDynamicSharedMemorySize, K1_SMEM);
    cudaFuncSetAttribute(k2_mma, cudaFuncAttributeMaxDynamicSharedMemorySize, K2_SMEM);

    k0_fused <<<768, 256>>>(W, gamma, beta, centers, sigmas, X);    // 1
    k1_frs   <<<NB/8, 128, K1_SMEM>>>(X);                           // 2
    k2_mma   <<<dim3(NB/128, OD), 256, K2_SMEM>>>(bias, out);       // 3
}